// round 8
// baseline (speedup 1.0000x reference)
#include <cuda_runtime.h>
#include <cuda_bf16.h>
#include <cuda_fp16.h>
#include <cstdint>

// ---------------------------------------------------------------------------
// EarthAttention3D: B_=960, L=144, C=192, H=6, hd=32, NUM_WINDOWS=64, W_WINS=15
// Round 8: FMA-pipe exp (softmax was MUFU-bound), fp16 ctx, fast bias gather.
// ---------------------------------------------------------------------------

#define NWIN   960
#define LTOK   144
#define CDIM   192
#define HEADS  6
#define HD     32
#define NW     64
#define WWINS  15
#define MTOT   (NWIN * LTOK)          // 138240
#define QK_SCALE 0.17677669529663687f

// ------------------------- scratch (device globals) ------------------------
__device__ float g_bias[NW * HEADS * LTOK * LTOK];
__device__ __half g_ctx[MTOT * CDIM];
__device__ __half g_Qh[NWIN * HEADS * LTOK * HD];
__device__ __half g_Ql[NWIN * HEADS * LTOK * HD];
__device__ __half g_Kh[NWIN * HEADS * LTOK * HD];
__device__ __half g_Vh[NWIN * HEADS * LTOK * HD];
__device__ __half g_Vl[NWIN * HEADS * LTOK * HD];
__device__ __half g_W1h[576 * 192];
__device__ __half g_W1l[576 * 192];
__device__ __half g_W2h[192 * 192];
__device__ __half g_W2l[192 * 192];

// ------------------------------ helpers ------------------------------------
__device__ __forceinline__ uint32_t smem_u32(const void* p) {
    uint32_t a;
    asm("{ .reg .u64 t; cvta.to.shared.u64 t, %1; cvt.u32.u64 %0, t; }"
        : "=r"(a) : "l"(p));
    return a;
}
__device__ __forceinline__ void hsplit(float v, __half& h, __half& l) {
    h = __float2half_rn(v);
    l = __float2half_rn(v - __half2float(h));
}
__device__ __forceinline__ uint32_t pack_h2(float a, float b) {
    __half2 t = __floats2half2_rn(a, b);
    return *reinterpret_cast<uint32_t*>(&t);
}
// exp(x) on the FMA pipe: 2^(x*log2e), rint + deg-5 poly + exponent splice.
__device__ __forceinline__ float fexp(float x) {
    float y = fmaxf(x * 1.4426950408889634f, -126.0f);
    float n = rintf(y);
    float f = y - n;
    float p = 0.0013333558f;
    p = fmaf(p, f, 0.009618129f);
    p = fmaf(p, f, 0.055504109f);
    p = fmaf(p, f, 0.24022651f);
    p = fmaf(p, f, 0.69314718f);
    p = fmaf(p, f, 1.0f);
    return __int_as_float(((int)n + 127) << 23) * p;
}

#define LDSM_X4(r0, r1, r2, r3, addr)                                          \
    asm volatile("ldmatrix.sync.aligned.m8n8.x4.shared.b16 {%0,%1,%2,%3}, [%4];" \
                 : "=r"(r0), "=r"(r1), "=r"(r2), "=r"(r3) : "r"(addr))

#define MMA_F16(d, a, b)                                                       \
    asm volatile("mma.sync.aligned.m16n8k16.row.col.f32.f16.f16.f32 "          \
                 "{%0,%1,%2,%3}, {%4,%5,%6,%7}, {%8,%9}, {%0,%1,%2,%3};"       \
                 : "+f"((d)[0]), "+f"((d)[1]), "+f"((d)[2]), "+f"((d)[3])      \
                 : "r"((a)[0]), "r"((a)[1]), "r"((a)[2]), "r"((a)[3]),         \
                   "r"((b)[0]), "r"((b)[1]))

// ---------------------------------------------------------------------------
// Prep: W [192][N] fp32 -> [N][192] fp16 hi/lo (transposed)
// ---------------------------------------------------------------------------
__global__ void splitW_kernel(const float* __restrict__ W,
                              __half* __restrict__ h, __half* __restrict__ l,
                              int N) {
    int idx = blockIdx.x * blockDim.x + threadIdx.x;
    if (idx >= N * 192) return;
    int n = idx / 192, k = idx - n * 192;
    __half hh, ll;
    hsplit(W[(size_t)k * N + n], hh, ll);
    h[idx] = hh; l[idx] = ll;
}

// ---------------------------------------------------------------------------
// K0: bias gather — per window, all 6 heads per thread (table row contiguous)
// ---------------------------------------------------------------------------
__global__ void bias_gather_kernel(const float* __restrict__ table,
                                   const int* __restrict__ pidx) {
    const int nw = blockIdx.x >> 2;
    const int part = blockIdx.x & 3;
    const size_t dbase = (size_t)nw * HEADS * (LTOK * LTOK);
    for (int i = part * 5184 + threadIdx.x; i < (part + 1) * 5184; i += 256) {
        const int pi = pidx[i];
        const float* src = table + (size_t)pi * (NW * HEADS) + nw * HEADS;
#pragma unroll
        for (int h = 0; h < HEADS; h++)
            g_bias[dbase + (size_t)h * (LTOK * LTOK) + i] = src[h];
    }
}

// ---------------------------------------------------------------------------
// fp16 2-pass GEMM (B split): C[M,Ntot] = A[M,192] @ (Bh+Bl)[Ntot,192]^T + bias
//   mode 0: A fp32 (convert in staging) -> Qh/Ql/Kh/Vh/Vl head-major.
//   mode 1: A fp16 (raw copy staging)   -> out fp32.
// ---------------------------------------------------------------------------
#define ASTR 200
#define GEMM_SMEM ((128 * ASTR + 2 * 64 * ASTR) * 2)  // 102400 B

__global__ __launch_bounds__(256, 2) void mma_gemm_kernel(
    const void* __restrict__ Ain, const __half* __restrict__ Bh,
    const __half* __restrict__ Bl, const float* __restrict__ bias,
    int ntiles, int mode, float* __restrict__ out) {
    extern __shared__ __align__(16) __half sb[];
    __half* sA  = sb;                      // [128][ASTR]
    __half* sBh = sb + 128 * ASTR;         // [64][ASTR]
    __half* sBl = sBh + 64 * ASTR;

    const int tid = threadIdx.x;
    const int warp = tid >> 5, lane = tid & 31;
    const int warpm = warp >> 1, warpn = warp & 1;
    const int m_blk = blockIdx.x * 128;

    if (mode == 1) {
        const __half* A = (const __half*)Ain;
        for (int i = tid; i < 128 * 24; i += 256) {
            int r = i / 24, c = (i % 24) * 8;
            *reinterpret_cast<uint4*>(&sA[r * ASTR + c]) =
                *reinterpret_cast<const uint4*>(&A[(size_t)(m_blk + r) * 192 + c]);
        }
    } else {
        const float* A = (const float*)Ain;
        for (int i = tid; i < 128 * 48; i += 256) {
            int r = i / 48, c4 = (i % 48) * 4;
            float4 v = *reinterpret_cast<const float4*>(&A[(size_t)(m_blk + r) * 192 + c4]);
            *reinterpret_cast<__half2*>(&sA[r * ASTR + c4]) = __floats2half2_rn(v.x, v.y);
            *reinterpret_cast<__half2*>(&sA[r * ASTR + c4 + 2]) = __floats2half2_rn(v.z, v.w);
        }
    }
    __syncthreads();

    const int lr = lane & 7, sel = lane >> 3;
    const int a_row_off = lr + (sel & 1) * 8;
    const int a_col_off = (sel >> 1) * 8;
    const int b_row_off = lr + (sel >> 1) * 8;
    const int b_col_off = (sel & 1) * 8;

    for (int nt = 0; nt < ntiles; nt++) {
        for (int i = tid; i < 64 * 24; i += 256) {
            int r = i / 24, c = (i % 24) * 8;
            *reinterpret_cast<uint4*>(&sBh[r * ASTR + c]) =
                *reinterpret_cast<const uint4*>(&Bh[(size_t)(nt * 64 + r) * 192 + c]);
            *reinterpret_cast<uint4*>(&sBl[r * ASTR + c]) =
                *reinterpret_cast<const uint4*>(&Bl[(size_t)(nt * 64 + r) * 192 + c]);
        }
        __syncthreads();

        float acc[2][4][4];
#pragma unroll
        for (int mt = 0; mt < 2; mt++)
#pragma unroll
            for (int t4 = 0; t4 < 4; t4++)
#pragma unroll
                for (int j = 0; j < 4; j++) acc[mt][t4][j] = 0.f;

#pragma unroll 4
        for (int ks = 0; ks < 12; ks++) {
            const int k0 = ks * 16;
            uint32_t a[2][4], bh[4][2], bl[4][2];
#pragma unroll
            for (int mt = 0; mt < 2; mt++) {
                int row = warpm * 32 + mt * 16 + a_row_off;
                LDSM_X4(a[mt][0], a[mt][1], a[mt][2], a[mt][3],
                        smem_u32(&sA[row * ASTR + k0 + a_col_off]));
            }
#pragma unroll
            for (int pr = 0; pr < 2; pr++) {
                int row = warpn * 32 + pr * 16 + b_row_off;
                LDSM_X4(bh[2 * pr][0], bh[2 * pr][1], bh[2 * pr + 1][0],
                        bh[2 * pr + 1][1],
                        smem_u32(&sBh[row * ASTR + k0 + b_col_off]));
                LDSM_X4(bl[2 * pr][0], bl[2 * pr][1], bl[2 * pr + 1][0],
                        bl[2 * pr + 1][1],
                        smem_u32(&sBl[row * ASTR + k0 + b_col_off]));
            }
#pragma unroll
            for (int mt = 0; mt < 2; mt++)
#pragma unroll
                for (int t4 = 0; t4 < 4; t4++) {
                    MMA_F16(acc[mt][t4], a[mt], bh[t4]);
                    MMA_F16(acc[mt][t4], a[mt], bl[t4]);
                }
        }

        const int qrow = lane >> 2;
        const int qcol = (lane & 3) * 2;
#pragma unroll
        for (int mt = 0; mt < 2; mt++) {
#pragma unroll
            for (int t4 = 0; t4 < 4; t4++) {
                const int col = nt * 64 + warpn * 32 + t4 * 8 + qcol;
                const float b0 = bias[col], b1 = bias[col + 1];
                const int r0 = m_blk + warpm * 32 + mt * 16 + qrow;
                float v00 = acc[mt][t4][0] + b0, v01 = acc[mt][t4][1] + b1;
                float v10 = acc[mt][t4][2] + b0, v11 = acc[mt][t4][3] + b1;
                if (mode == 1) {
                    *reinterpret_cast<float2*>(&out[(size_t)r0 * CDIM + col]) =
                        make_float2(v00, v01);
                    *reinterpret_cast<float2*>(&out[(size_t)(r0 + 8) * CDIM + col]) =
                        make_float2(v10, v11);
                } else {
                    const int t = col / CDIM;
                    const int rem = col - t * CDIM;
                    const int hh = rem >> 5, dd = rem & 31;
                    const int bi0 = r0 / LTOK, l0 = r0 - bi0 * LTOK;
                    const int r1 = r0 + 8;
                    const int bi1 = r1 / LTOK, l1 = r1 - bi1 * LTOK;
                    const size_t o0 = ((size_t)(bi0 * HEADS + hh) * LTOK + l0) * HD + dd;
                    const size_t o1 = ((size_t)(bi1 * HEADS + hh) * LTOK + l1) * HD + dd;
                    if (t == 0) {
                        __half ha, la, hb, lb;
                        hsplit(v00 * QK_SCALE, ha, la); hsplit(v01 * QK_SCALE, hb, lb);
                        *reinterpret_cast<__half2*>(g_Qh + o0) = __halves2half2(ha, hb);
                        *reinterpret_cast<__half2*>(g_Ql + o0) = __halves2half2(la, lb);
                        hsplit(v10 * QK_SCALE, ha, la); hsplit(v11 * QK_SCALE, hb, lb);
                        *reinterpret_cast<__half2*>(g_Qh + o1) = __halves2half2(ha, hb);
                        *reinterpret_cast<__half2*>(g_Ql + o1) = __halves2half2(la, lb);
                    } else if (t == 1) {
                        *reinterpret_cast<__half2*>(g_Kh + o0) =
                            __floats2half2_rn(v00, v01);
                        *reinterpret_cast<__half2*>(g_Kh + o1) =
                            __floats2half2_rn(v10, v11);
                    } else {
                        __half ha, la, hb, lb;
                        hsplit(v00, ha, la); hsplit(v01, hb, lb);
                        *reinterpret_cast<__half2*>(g_Vh + o0) = __halves2half2(ha, hb);
                        *reinterpret_cast<__half2*>(g_Vl + o0) = __halves2half2(la, lb);
                        hsplit(v10, ha, la); hsplit(v11, hb, lb);
                        *reinterpret_cast<__half2*>(g_Vh + o1) = __halves2half2(ha, hb);
                        *reinterpret_cast<__half2*>(g_Vl + o1) = __halves2half2(la, lb);
                    }
                }
            }
        }
        __syncthreads();
    }
}

// ---------------------------------------------------------------------------
// K2: register-resident mma attention, FMA-pipe softmax. 288 thr, 2 CTA/SM.
// ---------------------------------------------------------------------------
#define QSTR 40
#define VTSTR 152
#define ATTN_SMEM (3 * 144 * QSTR * 2 + 2 * 32 * VTSTR * 2)   // 54016 B

__global__ __launch_bounds__(288, 2) void attn_mma_kernel(const float* __restrict__ mask) {
    extern __shared__ __align__(16) char sraw[];
    __half* sQh = reinterpret_cast<__half*>(sraw);
    __half* sQl = sQh + 144 * QSTR;
    __half* sKh = sQl + 144 * QSTR;
    __half* sVh = sKh + 144 * QSTR;          // [32][VTSTR] transposed
    __half* sVl = sVh + 32 * VTSTR;

    const int bh = blockIdx.x;
    const int b = bh / HEADS, h = bh % HEADS;
    const int nw = b / WWINS;
    const int tid = threadIdx.x;
    const int warp = tid >> 5, lane = tid & 31;
    const size_t base = (size_t)bh * (LTOK * HD);

    for (int c = tid; c < 576; c += 288) {
        int l = c >> 2, dp = (c & 3) * 8;
        *reinterpret_cast<uint4*>(&sQh[l * QSTR + dp]) =
            *reinterpret_cast<const uint4*>(&g_Qh[base + l * 32 + dp]);
        *reinterpret_cast<uint4*>(&sQl[l * QSTR + dp]) =
            *reinterpret_cast<const uint4*>(&g_Ql[base + l * 32 + dp]);
        *reinterpret_cast<uint4*>(&sKh[l * QSTR + dp]) =
            *reinterpret_cast<const uint4*>(&g_Kh[base + l * 32 + dp]);
    }
    for (int i = tid; i < 2304; i += 288) {
        int l = i >> 4, d2 = (i & 15) * 2;
        __half2 vh = *reinterpret_cast<const __half2*>(&g_Vh[base + l * 32 + d2]);
        __half2 vl = *reinterpret_cast<const __half2*>(&g_Vl[base + l * 32 + d2]);
        sVh[d2 * VTSTR + l] = __low2half(vh);
        sVh[(d2 + 1) * VTSTR + l] = __high2half(vh);
        sVl[d2 * VTSTR + l] = __low2half(vl);
        sVl[(d2 + 1) * VTSTR + l] = __high2half(vl);
    }
    __syncthreads();

    const int lr = lane & 7, sel = lane >> 3;
    const int arow = lr + (sel & 1) * 8, acol = (sel >> 1) * 8;
    const int brow = lr + (sel >> 1) * 8, bcol = (sel & 1) * 8;
    const int g = lane >> 2, tg = lane & 3;

    uint32_t qh[2][4], ql[2][4];
#pragma unroll
    for (int ks = 0; ks < 2; ks++) {
        LDSM_X4(qh[ks][0], qh[ks][1], qh[ks][2], qh[ks][3],
                smem_u32(&sQh[(warp * 16 + arow) * QSTR + ks * 16 + acol]));
        LDSM_X4(ql[ks][0], ql[ks][1], ql[ks][2], ql[ks][3],
                smem_u32(&sQl[(warp * 16 + arow) * QSTR + ks * 16 + acol]));
    }

    float acc[18][4];
#pragma unroll
    for (int nb = 0; nb < 18; nb++)
#pragma unroll
        for (int j = 0; j < 4; j++) acc[nb][j] = 0.f;

#pragma unroll 3
    for (int nt = 0; nt < 9; nt++) {
#pragma unroll
        for (int ks = 0; ks < 2; ks++) {
            uint32_t kh[4];
            LDSM_X4(kh[0], kh[1], kh[2], kh[3],
                    smem_u32(&sKh[(nt * 16 + brow) * QSTR + ks * 16 + bcol]));
            MMA_F16(acc[2 * nt],     qh[ks], kh + 0);
            MMA_F16(acc[2 * nt + 1], qh[ks], kh + 2);
            MMA_F16(acc[2 * nt],     ql[ks], kh + 0);
            MMA_F16(acc[2 * nt + 1], ql[ks], kh + 2);
        }
    }

    const float* biasrow = g_bias + (size_t)(nw * HEADS + h) * (LTOK * LTOK);
    const float* maskrow = mask + (size_t)b * (LTOK * LTOK);
    const int r0 = warp * 16 + g;
    const int r1 = r0 + 8;
#pragma unroll
    for (int nb = 0; nb < 18; nb++) {
        const int cc = nb * 8 + tg * 2;
        float2 b0 = *reinterpret_cast<const float2*>(&biasrow[r0 * LTOK + cc]);
        float2 m0 = *reinterpret_cast<const float2*>(&maskrow[r0 * LTOK + cc]);
        float2 b1 = *reinterpret_cast<const float2*>(&biasrow[r1 * LTOK + cc]);
        float2 m1 = *reinterpret_cast<const float2*>(&maskrow[r1 * LTOK + cc]);
        acc[nb][0] += b0.x + m0.x;
        acc[nb][1] += b0.y + m0.y;
        acc[nb][2] += b1.x + m1.x;
        acc[nb][3] += b1.y + m1.y;
    }
    float mx0 = -1e30f, mx1 = -1e30f;
#pragma unroll
    for (int nb = 0; nb < 18; nb++) {
        mx0 = fmaxf(mx0, fmaxf(acc[nb][0], acc[nb][1]));
        mx1 = fmaxf(mx1, fmaxf(acc[nb][2], acc[nb][3]));
    }
    mx0 = fmaxf(mx0, __shfl_xor_sync(0xffffffffu, mx0, 1));
    mx0 = fmaxf(mx0, __shfl_xor_sync(0xffffffffu, mx0, 2));
    mx1 = fmaxf(mx1, __shfl_xor_sync(0xffffffffu, mx1, 1));
    mx1 = fmaxf(mx1, __shfl_xor_sync(0xffffffffu, mx1, 2));
    float s0 = 0.f, s1 = 0.f;
#pragma unroll
    for (int nb = 0; nb < 18; nb++) {
        acc[nb][0] = fexp(acc[nb][0] - mx0);
        acc[nb][1] = fexp(acc[nb][1] - mx0);
        acc[nb][2] = fexp(acc[nb][2] - mx1);
        acc[nb][3] = fexp(acc[nb][3] - mx1);
        s0 += acc[nb][0] + acc[nb][1];
        s1 += acc[nb][2] + acc[nb][3];
    }
    s0 += __shfl_xor_sync(0xffffffffu, s0, 1);
    s0 += __shfl_xor_sync(0xffffffffu, s0, 2);
    s1 += __shfl_xor_sync(0xffffffffu, s1, 1);
    s1 += __shfl_xor_sync(0xffffffffu, s1, 2);
    const float inv0 = 1.f / s0, inv1 = 1.f / s1;

    float o[4][4];
#pragma unroll
    for (int nb = 0; nb < 4; nb++)
#pragma unroll
        for (int j = 0; j < 4; j++) o[nb][j] = 0.f;

#pragma unroll 3
    for (int ks = 0; ks < 9; ks++) {
        uint32_t a[4];
        a[0] = pack_h2(acc[2 * ks][0] * inv0, acc[2 * ks][1] * inv0);
        a[1] = pack_h2(acc[2 * ks][2] * inv1, acc[2 * ks][3] * inv1);
        a[2] = pack_h2(acc[2 * ks + 1][0] * inv0, acc[2 * ks + 1][1] * inv0);
        a[3] = pack_h2(acc[2 * ks + 1][2] * inv1, acc[2 * ks + 1][3] * inv1);
#pragma unroll
        for (int ntv = 0; ntv < 2; ntv++) {
            uint32_t vh[4], vl[4];
            LDSM_X4(vh[0], vh[1], vh[2], vh[3],
                    smem_u32(&sVh[(ntv * 16 + brow) * VTSTR + ks * 16 + bcol]));
            LDSM_X4(vl[0], vl[1], vl[2], vl[3],
                    smem_u32(&sVl[(ntv * 16 + brow) * VTSTR + ks * 16 + bcol]));
            MMA_F16(o[2 * ntv],     a, vh + 0);
            MMA_F16(o[2 * ntv + 1], a, vh + 2);
            MMA_F16(o[2 * ntv],     a, vl + 0);
            MMA_F16(o[2 * ntv + 1], a, vl + 2);
        }
    }

#pragma unroll
    for (int nb = 0; nb < 4; nb++) {
        const int d0 = nb * 8 + tg * 2;
        const size_t off0 = ((size_t)b * LTOK + r0) * CDIM + h * HD + d0;
        const size_t off1 = ((size_t)b * LTOK + r1) * CDIM + h * HD + d0;
        *reinterpret_cast<__half2*>(&g_ctx[off0]) = __floats2half2_rn(o[nb][0], o[nb][1]);
        *reinterpret_cast<__half2*>(&g_ctx[off1]) = __floats2half2_rn(o[nb][2], o[nb][3]);
    }
}

// ---------------------------------------------------------------------------
extern "C" void kernel_launch(void* const* d_in, const int* in_sizes, int n_in,
                              void* d_out, int out_size) {
    const float* x    = (const float*)d_in[0];
    const float* mask = (const float*)d_in[1];
    const float* W1   = (const float*)d_in[2];
    const float* b1   = (const float*)d_in[3];
    const float* W2   = (const float*)d_in[4];
    const float* b2   = (const float*)d_in[5];
    const float* btab = (const float*)d_in[6];
    const int*   pidx = (const int*)d_in[7];
    float* out = (float*)d_out;
    (void)in_sizes; (void)n_in; (void)out_size;

    cudaFuncSetAttribute(mma_gemm_kernel,
                         cudaFuncAttributeMaxDynamicSharedMemorySize, GEMM_SMEM);
    cudaFuncSetAttribute(attn_mma_kernel,
                         cudaFuncAttributeMaxDynamicSharedMemorySize, ATTN_SMEM);

    __half *w1h, *w1l, *w2h, *w2l, *ctx;
    cudaGetSymbolAddress((void**)&w1h, g_W1h);
    cudaGetSymbolAddress((void**)&w1l, g_W1l);
    cudaGetSymbolAddress((void**)&w2h, g_W2h);
    cudaGetSymbolAddress((void**)&w2l, g_W2l);
    cudaGetSymbolAddress((void**)&ctx, g_ctx);

    splitW_kernel<<<(576 * 192 + 255) / 256, 256>>>(W1, w1h, w1l, 576);
    splitW_kernel<<<(192 * 192 + 255) / 256, 256>>>(W2, w2h, w2l, 192);
    bias_gather_kernel<<<NW * 4, 256>>>(btab, pidx);

    mma_gemm_kernel<<<MTOT / 128, 256, GEMM_SMEM>>>(x, w1h, w1l, b1, 9, 0, nullptr);
    attn_mma_kernel<<<NWIN * HEADS, 288, ATTN_SMEM>>>(mask);
    mma_gemm_kernel<<<MTOT / 128, 256, GEMM_SMEM>>>(ctx, w2h, w2l, b2, 3, 1, out);
}

// round 9
// speedup vs baseline: 1.0170x; 1.0170x over previous
#include <cuda_runtime.h>
#include <cuda_bf16.h>
#include <cuda_fp16.h>
#include <cstdint>

// ---------------------------------------------------------------------------
// EarthAttention3D: B_=960, L=144, C=192, H=6, hd=32, NUM_WINDOWS=64, W_WINS=15
// Round 9: fp16 bias + fp16 mask streams (attention was memory-bound on them),
// de-ALU'd GEMM epilogue. mma.sync fp16 2-pass everywhere.
// ---------------------------------------------------------------------------

#define NWIN   960
#define LTOK   144
#define CDIM   192
#define HEADS  6
#define HD     32
#define NW     64
#define WWINS  15
#define MTOT   (NWIN * LTOK)          // 138240
#define QK_SCALE 0.17677669529663687f

// ------------------------- scratch (device globals) ------------------------
__device__ __half g_bias[NW * HEADS * LTOK * LTOK];   // 16 MB, L2-resident
__device__ __half g_maskh[NWIN * LTOK * LTOK];        // 40 MB, L2-resident
__device__ __half g_ctx[MTOT * CDIM];
__device__ __half g_Qh[NWIN * HEADS * LTOK * HD];
__device__ __half g_Ql[NWIN * HEADS * LTOK * HD];
__device__ __half g_Kh[NWIN * HEADS * LTOK * HD];
__device__ __half g_Vh[NWIN * HEADS * LTOK * HD];
__device__ __half g_Vl[NWIN * HEADS * LTOK * HD];
__device__ __half g_W1h[576 * 192];
__device__ __half g_W1l[576 * 192];
__device__ __half g_W2h[192 * 192];
__device__ __half g_W2l[192 * 192];

// ------------------------------ helpers ------------------------------------
__device__ __forceinline__ uint32_t smem_u32(const void* p) {
    uint32_t a;
    asm("{ .reg .u64 t; cvta.to.shared.u64 t, %1; cvt.u32.u64 %0, t; }"
        : "=r"(a) : "l"(p));
    return a;
}
__device__ __forceinline__ void hsplit(float v, __half& h, __half& l) {
    h = __float2half_rn(v);
    l = __float2half_rn(v - __half2float(h));
}
__device__ __forceinline__ uint32_t pack_h2(float a, float b) {
    __half2 t = __floats2half2_rn(a, b);
    return *reinterpret_cast<uint32_t*>(&t);
}
// exp(x) on the FMA pipe
__device__ __forceinline__ float fexp(float x) {
    float y = fmaxf(x * 1.4426950408889634f, -126.0f);
    float n = rintf(y);
    float f = y - n;
    float p = 0.0013333558f;
    p = fmaf(p, f, 0.009618129f);
    p = fmaf(p, f, 0.055504109f);
    p = fmaf(p, f, 0.24022651f);
    p = fmaf(p, f, 0.69314718f);
    p = fmaf(p, f, 1.0f);
    return __int_as_float(((int)n + 127) << 23) * p;
}

#define LDSM_X4(r0, r1, r2, r3, addr)                                          \
    asm volatile("ldmatrix.sync.aligned.m8n8.x4.shared.b16 {%0,%1,%2,%3}, [%4];" \
                 : "=r"(r0), "=r"(r1), "=r"(r2), "=r"(r3) : "r"(addr))

#define MMA_F16(d, a, b)                                                       \
    asm volatile("mma.sync.aligned.m16n8k16.row.col.f32.f16.f16.f32 "          \
                 "{%0,%1,%2,%3}, {%4,%5,%6,%7}, {%8,%9}, {%0,%1,%2,%3};"       \
                 : "+f"((d)[0]), "+f"((d)[1]), "+f"((d)[2]), "+f"((d)[3])      \
                 : "r"((a)[0]), "r"((a)[1]), "r"((a)[2]), "r"((a)[3]),         \
                   "r"((b)[0]), "r"((b)[1]))

// ---------------------------------------------------------------------------
// Prep: W [192][N] fp32 -> [N][192] fp16 hi/lo (transposed)
// ---------------------------------------------------------------------------
__global__ void splitW_kernel(const float* __restrict__ W,
                              __half* __restrict__ h, __half* __restrict__ l,
                              int N) {
    int idx = blockIdx.x * blockDim.x + threadIdx.x;
    if (idx >= N * 192) return;
    int n = idx / 192, k = idx - n * 192;
    __half hh, ll;
    hsplit(W[(size_t)k * N + n], hh, ll);
    h[idx] = hh; l[idx] = ll;
}

// mask fp32 -> fp16
__global__ void mask2h_kernel(const float* __restrict__ m, int n4) {
    int i = blockIdx.x * blockDim.x + threadIdx.x;
    if (i >= n4) return;
    float4 v = reinterpret_cast<const float4*>(m)[i];
    reinterpret_cast<__half2*>(g_maskh)[2 * i]     = __floats2half2_rn(v.x, v.y);
    reinterpret_cast<__half2*>(g_maskh)[2 * i + 1] = __floats2half2_rn(v.z, v.w);
}

// ---------------------------------------------------------------------------
// K0: bias gather (fp16 out), per window, 6 heads per thread
// ---------------------------------------------------------------------------
__global__ void bias_gather_kernel(const float* __restrict__ table,
                                   const int* __restrict__ pidx) {
    const int nw = blockIdx.x >> 2;
    const int part = blockIdx.x & 3;
    const size_t dbase = (size_t)nw * HEADS * (LTOK * LTOK);
    for (int i = part * 5184 + threadIdx.x; i < (part + 1) * 5184; i += 256) {
        const int pi = pidx[i];
        const float* src = table + (size_t)pi * (NW * HEADS) + nw * HEADS;
#pragma unroll
        for (int h = 0; h < HEADS; h++)
            g_bias[dbase + (size_t)h * (LTOK * LTOK) + i] = __float2half_rn(src[h]);
    }
}

// ---------------------------------------------------------------------------
// fp16 2-pass GEMM (B split). mode 0: A fp32, scatter Q/K/V; mode 1: A fp16,
// out fp32. Epilogue divisions hoisted.
// ---------------------------------------------------------------------------
#define ASTR 200
#define GEMM_SMEM ((128 * ASTR + 2 * 64 * ASTR) * 2)  // 102400 B

__global__ __launch_bounds__(256, 2) void mma_gemm_kernel(
    const void* __restrict__ Ain, const __half* __restrict__ Bh,
    const __half* __restrict__ Bl, const float* __restrict__ bias,
    int ntiles, int mode, float* __restrict__ out) {
    extern __shared__ __align__(16) __half sb[];
    __half* sA  = sb;                      // [128][ASTR]
    __half* sBh = sb + 128 * ASTR;         // [64][ASTR]
    __half* sBl = sBh + 64 * ASTR;

    const int tid = threadIdx.x;
    const int warp = tid >> 5, lane = tid & 31;
    const int warpm = warp >> 1, warpn = warp & 1;
    const int m_blk = blockIdx.x * 128;

    if (mode == 1) {
        const __half* A = (const __half*)Ain;
        for (int i = tid; i < 128 * 24; i += 256) {
            int r = i / 24, c = (i % 24) * 8;
            *reinterpret_cast<uint4*>(&sA[r * ASTR + c]) =
                *reinterpret_cast<const uint4*>(&A[(size_t)(m_blk + r) * 192 + c]);
        }
    } else {
        const float* A = (const float*)Ain;
        for (int i = tid; i < 128 * 48; i += 256) {
            int r = i / 48, c4 = (i % 48) * 4;
            float4 v = *reinterpret_cast<const float4*>(&A[(size_t)(m_blk + r) * 192 + c4]);
            *reinterpret_cast<__half2*>(&sA[r * ASTR + c4]) = __floats2half2_rn(v.x, v.y);
            *reinterpret_cast<__half2*>(&sA[r * ASTR + c4 + 2]) = __floats2half2_rn(v.z, v.w);
        }
    }
    __syncthreads();

    const int lr = lane & 7, sel = lane >> 3;
    const int a_row_off = lr + (sel & 1) * 8;
    const int a_col_off = (sel >> 1) * 8;
    const int b_row_off = lr + (sel >> 1) * 8;
    const int b_col_off = (sel & 1) * 8;
    const int qrow = lane >> 2;
    const int qcol = (lane & 3) * 2;

    // hoisted row indices for mode-0 scatter: i = mt*2 + halfrow
    int rbi[4], rli[4];
#pragma unroll
    for (int i = 0; i < 4; i++) {
        int r = m_blk + warpm * 32 + (i >> 1) * 16 + (i & 1) * 8 + qrow;
        rbi[i] = r / LTOK;
        rli[i] = r - rbi[i] * LTOK;
    }

    for (int nt = 0; nt < ntiles; nt++) {
        for (int i = tid; i < 64 * 24; i += 256) {
            int r = i / 24, c = (i % 24) * 8;
            *reinterpret_cast<uint4*>(&sBh[r * ASTR + c]) =
                *reinterpret_cast<const uint4*>(&Bh[(size_t)(nt * 64 + r) * 192 + c]);
            *reinterpret_cast<uint4*>(&sBl[r * ASTR + c]) =
                *reinterpret_cast<const uint4*>(&Bl[(size_t)(nt * 64 + r) * 192 + c]);
        }
        __syncthreads();

        float acc[2][4][4];
#pragma unroll
        for (int mt = 0; mt < 2; mt++)
#pragma unroll
            for (int t4 = 0; t4 < 4; t4++)
#pragma unroll
                for (int j = 0; j < 4; j++) acc[mt][t4][j] = 0.f;

#pragma unroll 4
        for (int ks = 0; ks < 12; ks++) {
            const int k0 = ks * 16;
            uint32_t a[2][4], bh[4][2], bl[4][2];
#pragma unroll
            for (int mt = 0; mt < 2; mt++) {
                int row = warpm * 32 + mt * 16 + a_row_off;
                LDSM_X4(a[mt][0], a[mt][1], a[mt][2], a[mt][3],
                        smem_u32(&sA[row * ASTR + k0 + a_col_off]));
            }
#pragma unroll
            for (int pr = 0; pr < 2; pr++) {
                int row = warpn * 32 + pr * 16 + b_row_off;
                LDSM_X4(bh[2 * pr][0], bh[2 * pr][1], bh[2 * pr + 1][0],
                        bh[2 * pr + 1][1],
                        smem_u32(&sBh[row * ASTR + k0 + b_col_off]));
                LDSM_X4(bl[2 * pr][0], bl[2 * pr][1], bl[2 * pr + 1][0],
                        bl[2 * pr + 1][1],
                        smem_u32(&sBl[row * ASTR + k0 + b_col_off]));
            }
#pragma unroll
            for (int mt = 0; mt < 2; mt++)
#pragma unroll
                for (int t4 = 0; t4 < 4; t4++) {
                    MMA_F16(acc[mt][t4], a[mt], bh[t4]);
                    MMA_F16(acc[mt][t4], a[mt], bl[t4]);
                }
        }

        if (mode == 1) {
#pragma unroll
            for (int t4 = 0; t4 < 4; t4++) {
                const int col = nt * 64 + warpn * 32 + t4 * 8 + qcol;
                const float b0 = bias[col], b1 = bias[col + 1];
#pragma unroll
                for (int mt = 0; mt < 2; mt++) {
                    const int r0 = m_blk + warpm * 32 + mt * 16 + qrow;
                    *reinterpret_cast<float2*>(&out[(size_t)r0 * CDIM + col]) =
                        make_float2(acc[mt][t4][0] + b0, acc[mt][t4][1] + b1);
                    *reinterpret_cast<float2*>(&out[(size_t)(r0 + 8) * CDIM + col]) =
                        make_float2(acc[mt][t4][2] + b0, acc[mt][t4][3] + b1);
                }
            }
        } else {
#pragma unroll
            for (int t4 = 0; t4 < 4; t4++) {
                const int col = nt * 64 + warpn * 32 + t4 * 8 + qcol;
                const int t = (col >= 2 * CDIM) ? 2 : ((col >= CDIM) ? 1 : 0);
                const int rem = col - t * CDIM;
                const int hh = rem >> 5, dd = rem & 31;
                const float b0 = bias[col], b1 = bias[col + 1];
#pragma unroll
                for (int mt = 0; mt < 2; mt++) {
                    const int i0 = mt * 2, i1 = mt * 2 + 1;
                    const size_t o0 =
                        ((size_t)(rbi[i0] * HEADS + hh) * LTOK + rli[i0]) * HD + dd;
                    const size_t o1 =
                        ((size_t)(rbi[i1] * HEADS + hh) * LTOK + rli[i1]) * HD + dd;
                    float v00 = acc[mt][t4][0] + b0, v01 = acc[mt][t4][1] + b1;
                    float v10 = acc[mt][t4][2] + b0, v11 = acc[mt][t4][3] + b1;
                    if (t == 0) {
                        __half ha, la, hb, lb;
                        hsplit(v00 * QK_SCALE, ha, la); hsplit(v01 * QK_SCALE, hb, lb);
                        *reinterpret_cast<__half2*>(g_Qh + o0) = __halves2half2(ha, hb);
                        *reinterpret_cast<__half2*>(g_Ql + o0) = __halves2half2(la, lb);
                        hsplit(v10 * QK_SCALE, ha, la); hsplit(v11 * QK_SCALE, hb, lb);
                        *reinterpret_cast<__half2*>(g_Qh + o1) = __halves2half2(ha, hb);
                        *reinterpret_cast<__half2*>(g_Ql + o1) = __halves2half2(la, lb);
                    } else if (t == 1) {
                        *reinterpret_cast<__half2*>(g_Kh + o0) =
                            __floats2half2_rn(v00, v01);
                        *reinterpret_cast<__half2*>(g_Kh + o1) =
                            __floats2half2_rn(v10, v11);
                    } else {
                        __half ha, la, hb, lb;
                        hsplit(v00, ha, la); hsplit(v01, hb, lb);
                        *reinterpret_cast<__half2*>(g_Vh + o0) = __halves2half2(ha, hb);
                        *reinterpret_cast<__half2*>(g_Vl + o0) = __halves2half2(la, lb);
                        hsplit(v10, ha, la); hsplit(v11, hb, lb);
                        *reinterpret_cast<__half2*>(g_Vh + o1) = __halves2half2(ha, hb);
                        *reinterpret_cast<__half2*>(g_Vl + o1) = __halves2half2(la, lb);
                    }
                }
            }
        }
        __syncthreads();
    }
}

// ---------------------------------------------------------------------------
// K2: register-resident mma attention; fp16 bias/mask streams. 288 thr, 2/SM.
// ---------------------------------------------------------------------------
#define QSTR 40
#define VTSTR 152
#define ATTN_SMEM (3 * 144 * QSTR * 2 + 2 * 32 * VTSTR * 2)   // 54016 B

__global__ __launch_bounds__(288, 2) void attn_mma_kernel() {
    extern __shared__ __align__(16) char sraw[];
    __half* sQh = reinterpret_cast<__half*>(sraw);
    __half* sQl = sQh + 144 * QSTR;
    __half* sKh = sQl + 144 * QSTR;
    __half* sVh = sKh + 144 * QSTR;          // [32][VTSTR] transposed
    __half* sVl = sVh + 32 * VTSTR;

    const int bh = blockIdx.x;
    const int b = bh / HEADS, h = bh % HEADS;
    const int nw = b / WWINS;
    const int tid = threadIdx.x;
    const int warp = tid >> 5, lane = tid & 31;
    const size_t base = (size_t)bh * (LTOK * HD);

    for (int c = tid; c < 576; c += 288) {
        int l = c >> 2, dp = (c & 3) * 8;
        *reinterpret_cast<uint4*>(&sQh[l * QSTR + dp]) =
            *reinterpret_cast<const uint4*>(&g_Qh[base + l * 32 + dp]);
        *reinterpret_cast<uint4*>(&sQl[l * QSTR + dp]) =
            *reinterpret_cast<const uint4*>(&g_Ql[base + l * 32 + dp]);
        *reinterpret_cast<uint4*>(&sKh[l * QSTR + dp]) =
            *reinterpret_cast<const uint4*>(&g_Kh[base + l * 32 + dp]);
    }
    for (int i = tid; i < 2304; i += 288) {
        int l = i >> 4, d2 = (i & 15) * 2;
        __half2 vh = *reinterpret_cast<const __half2*>(&g_Vh[base + l * 32 + d2]);
        __half2 vl = *reinterpret_cast<const __half2*>(&g_Vl[base + l * 32 + d2]);
        sVh[d2 * VTSTR + l] = __low2half(vh);
        sVh[(d2 + 1) * VTSTR + l] = __high2half(vh);
        sVl[d2 * VTSTR + l] = __low2half(vl);
        sVl[(d2 + 1) * VTSTR + l] = __high2half(vl);
    }
    __syncthreads();

    const int lr = lane & 7, sel = lane >> 3;
    const int arow = lr + (sel & 1) * 8, acol = (sel >> 1) * 8;
    const int brow = lr + (sel >> 1) * 8, bcol = (sel & 1) * 8;
    const int g = lane >> 2, tg = lane & 3;

    uint32_t qh[2][4], ql[2][4];
#pragma unroll
    for (int ks = 0; ks < 2; ks++) {
        LDSM_X4(qh[ks][0], qh[ks][1], qh[ks][2], qh[ks][3],
                smem_u32(&sQh[(warp * 16 + arow) * QSTR + ks * 16 + acol]));
        LDSM_X4(ql[ks][0], ql[ks][1], ql[ks][2], ql[ks][3],
                smem_u32(&sQl[(warp * 16 + arow) * QSTR + ks * 16 + acol]));
    }

    float acc[18][4];
#pragma unroll
    for (int nb = 0; nb < 18; nb++)
#pragma unroll
        for (int j = 0; j < 4; j++) acc[nb][j] = 0.f;

#pragma unroll 3
    for (int nt = 0; nt < 9; nt++) {
#pragma unroll
        for (int ks = 0; ks < 2; ks++) {
            uint32_t kh[4];
            LDSM_X4(kh[0], kh[1], kh[2], kh[3],
                    smem_u32(&sKh[(nt * 16 + brow) * QSTR + ks * 16 + bcol]));
            MMA_F16(acc[2 * nt],     qh[ks], kh + 0);
            MMA_F16(acc[2 * nt + 1], qh[ks], kh + 2);
            MMA_F16(acc[2 * nt],     ql[ks], kh + 0);
            MMA_F16(acc[2 * nt + 1], ql[ks], kh + 2);
        }
    }

    const __half* biasrow = g_bias + (size_t)(nw * HEADS + h) * (LTOK * LTOK);
    const __half* maskrow = g_maskh + (size_t)b * (LTOK * LTOK);
    const int r0 = warp * 16 + g;
    const int r1 = r0 + 8;
#pragma unroll
    for (int nb = 0; nb < 18; nb++) {
        const int cc = nb * 8 + tg * 2;
        float2 b0 = __half22float2(
            *reinterpret_cast<const __half2*>(&biasrow[r0 * LTOK + cc]));
        float2 m0 = __half22float2(
            *reinterpret_cast<const __half2*>(&maskrow[r0 * LTOK + cc]));
        float2 b1 = __half22float2(
            *reinterpret_cast<const __half2*>(&biasrow[r1 * LTOK + cc]));
        float2 m1 = __half22float2(
            *reinterpret_cast<const __half2*>(&maskrow[r1 * LTOK + cc]));
        acc[nb][0] += b0.x + m0.x;
        acc[nb][1] += b0.y + m0.y;
        acc[nb][2] += b1.x + m1.x;
        acc[nb][3] += b1.y + m1.y;
    }
    float mx0 = -1e30f, mx1 = -1e30f;
#pragma unroll
    for (int nb = 0; nb < 18; nb++) {
        mx0 = fmaxf(mx0, fmaxf(acc[nb][0], acc[nb][1]));
        mx1 = fmaxf(mx1, fmaxf(acc[nb][2], acc[nb][3]));
    }
    mx0 = fmaxf(mx0, __shfl_xor_sync(0xffffffffu, mx0, 1));
    mx0 = fmaxf(mx0, __shfl_xor_sync(0xffffffffu, mx0, 2));
    mx1 = fmaxf(mx1, __shfl_xor_sync(0xffffffffu, mx1, 1));
    mx1 = fmaxf(mx1, __shfl_xor_sync(0xffffffffu, mx1, 2));
    float s0 = 0.f, s1 = 0.f;
#pragma unroll
    for (int nb = 0; nb < 18; nb++) {
        acc[nb][0] = fexp(acc[nb][0] - mx0);
        acc[nb][1] = fexp(acc[nb][1] - mx0);
        acc[nb][2] = fexp(acc[nb][2] - mx1);
        acc[nb][3] = fexp(acc[nb][3] - mx1);
        s0 += acc[nb][0] + acc[nb][1];
        s1 += acc[nb][2] + acc[nb][3];
    }
    s0 += __shfl_xor_sync(0xffffffffu, s0, 1);
    s0 += __shfl_xor_sync(0xffffffffu, s0, 2);
    s1 += __shfl_xor_sync(0xffffffffu, s1, 1);
    s1 += __shfl_xor_sync(0xffffffffu, s1, 2);
    const float inv0 = 1.f / s0, inv1 = 1.f / s1;

    float o[4][4];
#pragma unroll
    for (int nb = 0; nb < 4; nb++)
#pragma unroll
        for (int j = 0; j < 4; j++) o[nb][j] = 0.f;

#pragma unroll 3
    for (int ks = 0; ks < 9; ks++) {
        uint32_t a[4];
        a[0] = pack_h2(acc[2 * ks][0] * inv0, acc[2 * ks][1] * inv0);
        a[1] = pack_h2(acc[2 * ks][2] * inv1, acc[2 * ks][3] * inv1);
        a[2] = pack_h2(acc[2 * ks + 1][0] * inv0, acc[2 * ks + 1][1] * inv0);
        a[3] = pack_h2(acc[2 * ks + 1][2] * inv1, acc[2 * ks + 1][3] * inv1);
#pragma unroll
        for (int ntv = 0; ntv < 2; ntv++) {
            uint32_t vh[4], vl[4];
            LDSM_X4(vh[0], vh[1], vh[2], vh[3],
                    smem_u32(&sVh[(ntv * 16 + brow) * VTSTR + ks * 16 + bcol]));
            LDSM_X4(vl[0], vl[1], vl[2], vl[3],
                    smem_u32(&sVl[(ntv * 16 + brow) * VTSTR + ks * 16 + bcol]));
            MMA_F16(o[2 * ntv],     a, vh + 0);
            MMA_F16(o[2 * ntv + 1], a, vh + 2);
            MMA_F16(o[2 * ntv],     a, vl + 0);
            MMA_F16(o[2 * ntv + 1], a, vl + 2);
        }
    }

#pragma unroll
    for (int nb = 0; nb < 4; nb++) {
        const int d0 = nb * 8 + tg * 2;
        const size_t off0 = ((size_t)b * LTOK + r0) * CDIM + h * HD + d0;
        const size_t off1 = ((size_t)b * LTOK + r1) * CDIM + h * HD + d0;
        *reinterpret_cast<__half2*>(&g_ctx[off0]) = __floats2half2_rn(o[nb][0], o[nb][1]);
        *reinterpret_cast<__half2*>(&g_ctx[off1]) = __floats2half2_rn(o[nb][2], o[nb][3]);
    }
}

// ---------------------------------------------------------------------------
extern "C" void kernel_launch(void* const* d_in, const int* in_sizes, int n_in,
                              void* d_out, int out_size) {
    const float* x    = (const float*)d_in[0];
    const float* mask = (const float*)d_in[1];
    const float* W1   = (const float*)d_in[2];
    const float* b1   = (const float*)d_in[3];
    const float* W2   = (const float*)d_in[4];
    const float* b2   = (const float*)d_in[5];
    const float* btab = (const float*)d_in[6];
    const int*   pidx = (const int*)d_in[7];
    float* out = (float*)d_out;
    (void)in_sizes; (void)n_in; (void)out_size;

    cudaFuncSetAttribute(mma_gemm_kernel,
                         cudaFuncAttributeMaxDynamicSharedMemorySize, GEMM_SMEM);
    cudaFuncSetAttribute(attn_mma_kernel,
                         cudaFuncAttributeMaxDynamicSharedMemorySize, ATTN_SMEM);

    __half *w1h, *w1l, *w2h, *w2l, *ctx;
    cudaGetSymbolAddress((void**)&w1h, g_W1h);
    cudaGetSymbolAddress((void**)&w1l, g_W1l);
    cudaGetSymbolAddress((void**)&w2h, g_W2h);
    cudaGetSymbolAddress((void**)&w2l, g_W2l);
    cudaGetSymbolAddress((void**)&ctx, g_ctx);

    splitW_kernel<<<(576 * 192 + 255) / 256, 256>>>(W1, w1h, w1l, 576);
    splitW_kernel<<<(192 * 192 + 255) / 256, 256>>>(W2, w2h, w2l, 192);
    mask2h_kernel<<<(NWIN * LTOK * LTOK / 4 + 255) / 256, 256>>>(mask,
                                                                 NWIN * LTOK * LTOK / 4);
    bias_gather_kernel<<<NW * 4, 256>>>(btab, pidx);

    mma_gemm_kernel<<<MTOT / 128, 256, GEMM_SMEM>>>(x, w1h, w1l, b1, 9, 0, nullptr);
    attn_mma_kernel<<<NWIN * HEADS, 288, ATTN_SMEM>>>();
    mma_gemm_kernel<<<MTOT / 128, 256, GEMM_SMEM>>>(ctx, w2h, w2l, b2, 3, 1, out);
}

// round 10
// speedup vs baseline: 1.2086x; 1.1884x over previous
#include <cuda_runtime.h>
#include <cuda_bf16.h>
#include <cuda_fp16.h>
#include <cstdint>

// ---------------------------------------------------------------------------
// EarthAttention3D: B_=960, L=144, C=192, H=6, hd=32, NUM_WINDOWS=64, W_WINS=15
// Round 10: online-softmax (3x48-col chunks) attention -> acc regs 72->24,
// no spills under launch_bounds(288,2). GEMMs as R9.
// ---------------------------------------------------------------------------

#define NWIN   960
#define LTOK   144
#define CDIM   192
#define HEADS  6
#define HD     32
#define NW     64
#define WWINS  15
#define MTOT   (NWIN * LTOK)          // 138240
#define QK_SCALE 0.17677669529663687f

// ------------------------- scratch (device globals) ------------------------
__device__ __half g_bias[NW * HEADS * LTOK * LTOK];
__device__ __half g_maskh[NWIN * LTOK * LTOK];
__device__ __half g_ctx[MTOT * CDIM];
__device__ __half g_Qh[NWIN * HEADS * LTOK * HD];
__device__ __half g_Ql[NWIN * HEADS * LTOK * HD];
__device__ __half g_Kh[NWIN * HEADS * LTOK * HD];
__device__ __half g_Vh[NWIN * HEADS * LTOK * HD];
__device__ __half g_Vl[NWIN * HEADS * LTOK * HD];
__device__ __half g_W1h[576 * 192];
__device__ __half g_W1l[576 * 192];
__device__ __half g_W2h[192 * 192];
__device__ __half g_W2l[192 * 192];

// ------------------------------ helpers ------------------------------------
__device__ __forceinline__ uint32_t smem_u32(const void* p) {
    uint32_t a;
    asm("{ .reg .u64 t; cvta.to.shared.u64 t, %1; cvt.u32.u64 %0, t; }"
        : "=r"(a) : "l"(p));
    return a;
}
__device__ __forceinline__ void hsplit(float v, __half& h, __half& l) {
    h = __float2half_rn(v);
    l = __float2half_rn(v - __half2float(h));
}
__device__ __forceinline__ uint32_t pack_h2(float a, float b) {
    __half2 t = __floats2half2_rn(a, b);
    return *reinterpret_cast<uint32_t*>(&t);
}
// exp(x) on the FMA pipe
__device__ __forceinline__ float fexp(float x) {
    float y = fmaxf(x * 1.4426950408889634f, -126.0f);
    float n = rintf(y);
    float f = y - n;
    float p = 0.0013333558f;
    p = fmaf(p, f, 0.009618129f);
    p = fmaf(p, f, 0.055504109f);
    p = fmaf(p, f, 0.24022651f);
    p = fmaf(p, f, 0.69314718f);
    p = fmaf(p, f, 1.0f);
    return __int_as_float(((int)n + 127) << 23) * p;
}

#define LDSM_X4(r0, r1, r2, r3, addr)                                          \
    asm volatile("ldmatrix.sync.aligned.m8n8.x4.shared.b16 {%0,%1,%2,%3}, [%4];" \
                 : "=r"(r0), "=r"(r1), "=r"(r2), "=r"(r3) : "r"(addr))

#define MMA_F16(d, a, b)                                                       \
    asm volatile("mma.sync.aligned.m16n8k16.row.col.f32.f16.f16.f32 "          \
                 "{%0,%1,%2,%3}, {%4,%5,%6,%7}, {%8,%9}, {%0,%1,%2,%3};"       \
                 : "+f"((d)[0]), "+f"((d)[1]), "+f"((d)[2]), "+f"((d)[3])      \
                 : "r"((a)[0]), "r"((a)[1]), "r"((a)[2]), "r"((a)[3]),         \
                   "r"((b)[0]), "r"((b)[1]))

// ---------------------------------------------------------------------------
// Prep: W [192][N] fp32 -> [N][192] fp16 hi/lo (transposed)
// ---------------------------------------------------------------------------
__global__ void splitW_kernel(const float* __restrict__ W,
                              __half* __restrict__ h, __half* __restrict__ l,
                              int N) {
    int idx = blockIdx.x * blockDim.x + threadIdx.x;
    if (idx >= N * 192) return;
    int n = idx / 192, k = idx - n * 192;
    __half hh, ll;
    hsplit(W[(size_t)k * N + n], hh, ll);
    h[idx] = hh; l[idx] = ll;
}

// mask fp32 -> fp16
__global__ void mask2h_kernel(const float* __restrict__ m, int n4) {
    int i = blockIdx.x * blockDim.x + threadIdx.x;
    if (i >= n4) return;
    float4 v = reinterpret_cast<const float4*>(m)[i];
    reinterpret_cast<__half2*>(g_maskh)[2 * i]     = __floats2half2_rn(v.x, v.y);
    reinterpret_cast<__half2*>(g_maskh)[2 * i + 1] = __floats2half2_rn(v.z, v.w);
}

// ---------------------------------------------------------------------------
// K0: bias gather (fp16 out), split 8x per window
// ---------------------------------------------------------------------------
__global__ void bias_gather_kernel(const float* __restrict__ table,
                                   const int* __restrict__ pidx) {
    const int nw = blockIdx.x >> 3;
    const int part = blockIdx.x & 7;
    const size_t dbase = (size_t)nw * HEADS * (LTOK * LTOK);
    for (int i = part * 2592 + threadIdx.x; i < (part + 1) * 2592; i += 256) {
        const int pi = pidx[i];
        const float* src = table + (size_t)pi * (NW * HEADS) + nw * HEADS;
#pragma unroll
        for (int h = 0; h < HEADS; h++)
            g_bias[dbase + (size_t)h * (LTOK * LTOK) + i] = __float2half_rn(src[h]);
    }
}

// ---------------------------------------------------------------------------
// fp16 2-pass GEMM (B split). mode 0: A fp32, scatter Q/K/V; mode 1: A fp16,
// out fp32.
// ---------------------------------------------------------------------------
#define ASTR 200
#define GEMM_SMEM ((128 * ASTR + 2 * 64 * ASTR) * 2)  // 102400 B

__global__ __launch_bounds__(256, 2) void mma_gemm_kernel(
    const void* __restrict__ Ain, const __half* __restrict__ Bh,
    const __half* __restrict__ Bl, const float* __restrict__ bias,
    int ntiles, int mode, float* __restrict__ out) {
    extern __shared__ __align__(16) __half sb[];
    __half* sA  = sb;                      // [128][ASTR]
    __half* sBh = sb + 128 * ASTR;         // [64][ASTR]
    __half* sBl = sBh + 64 * ASTR;

    const int tid = threadIdx.x;
    const int warp = tid >> 5, lane = tid & 31;
    const int warpm = warp >> 1, warpn = warp & 1;
    const int m_blk = blockIdx.x * 128;

    if (mode == 1) {
        const __half* A = (const __half*)Ain;
        for (int i = tid; i < 128 * 24; i += 256) {
            int r = i / 24, c = (i % 24) * 8;
            *reinterpret_cast<uint4*>(&sA[r * ASTR + c]) =
                *reinterpret_cast<const uint4*>(&A[(size_t)(m_blk + r) * 192 + c]);
        }
    } else {
        const float* A = (const float*)Ain;
        for (int i = tid; i < 128 * 48; i += 256) {
            int r = i / 48, c4 = (i % 48) * 4;
            float4 v = *reinterpret_cast<const float4*>(&A[(size_t)(m_blk + r) * 192 + c4]);
            *reinterpret_cast<__half2*>(&sA[r * ASTR + c4]) = __floats2half2_rn(v.x, v.y);
            *reinterpret_cast<__half2*>(&sA[r * ASTR + c4 + 2]) = __floats2half2_rn(v.z, v.w);
        }
    }
    __syncthreads();

    const int lr = lane & 7, sel = lane >> 3;
    const int a_row_off = lr + (sel & 1) * 8;
    const int a_col_off = (sel >> 1) * 8;
    const int b_row_off = lr + (sel >> 1) * 8;
    const int b_col_off = (sel & 1) * 8;
    const int qrow = lane >> 2;
    const int qcol = (lane & 3) * 2;

    int rbi[4], rli[4];
#pragma unroll
    for (int i = 0; i < 4; i++) {
        int r = m_blk + warpm * 32 + (i >> 1) * 16 + (i & 1) * 8 + qrow;
        rbi[i] = r / LTOK;
        rli[i] = r - rbi[i] * LTOK;
    }

    for (int nt = 0; nt < ntiles; nt++) {
        for (int i = tid; i < 64 * 24; i += 256) {
            int r = i / 24, c = (i % 24) * 8;
            *reinterpret_cast<uint4*>(&sBh[r * ASTR + c]) =
                *reinterpret_cast<const uint4*>(&Bh[(size_t)(nt * 64 + r) * 192 + c]);
            *reinterpret_cast<uint4*>(&sBl[r * ASTR + c]) =
                *reinterpret_cast<const uint4*>(&Bl[(size_t)(nt * 64 + r) * 192 + c]);
        }
        __syncthreads();

        float acc[2][4][4];
#pragma unroll
        for (int mt = 0; mt < 2; mt++)
#pragma unroll
            for (int t4 = 0; t4 < 4; t4++)
#pragma unroll
                for (int j = 0; j < 4; j++) acc[mt][t4][j] = 0.f;

#pragma unroll 4
        for (int ks = 0; ks < 12; ks++) {
            const int k0 = ks * 16;
            uint32_t a[2][4], bh[4][2], bl[4][2];
#pragma unroll
            for (int mt = 0; mt < 2; mt++) {
                int row = warpm * 32 + mt * 16 + a_row_off;
                LDSM_X4(a[mt][0], a[mt][1], a[mt][2], a[mt][3],
                        smem_u32(&sA[row * ASTR + k0 + a_col_off]));
            }
#pragma unroll
            for (int pr = 0; pr < 2; pr++) {
                int row = warpn * 32 + pr * 16 + b_row_off;
                LDSM_X4(bh[2 * pr][0], bh[2 * pr][1], bh[2 * pr + 1][0],
                        bh[2 * pr + 1][1],
                        smem_u32(&sBh[row * ASTR + k0 + b_col_off]));
                LDSM_X4(bl[2 * pr][0], bl[2 * pr][1], bl[2 * pr + 1][0],
                        bl[2 * pr + 1][1],
                        smem_u32(&sBl[row * ASTR + k0 + b_col_off]));
            }
#pragma unroll
            for (int mt = 0; mt < 2; mt++)
#pragma unroll
                for (int t4 = 0; t4 < 4; t4++) {
                    MMA_F16(acc[mt][t4], a[mt], bh[t4]);
                    MMA_F16(acc[mt][t4], a[mt], bl[t4]);
                }
        }

        if (mode == 1) {
#pragma unroll
            for (int t4 = 0; t4 < 4; t4++) {
                const int col = nt * 64 + warpn * 32 + t4 * 8 + qcol;
                const float b0 = bias[col], b1 = bias[col + 1];
#pragma unroll
                for (int mt = 0; mt < 2; mt++) {
                    const int r0 = m_blk + warpm * 32 + mt * 16 + qrow;
                    *reinterpret_cast<float2*>(&out[(size_t)r0 * CDIM + col]) =
                        make_float2(acc[mt][t4][0] + b0, acc[mt][t4][1] + b1);
                    *reinterpret_cast<float2*>(&out[(size_t)(r0 + 8) * CDIM + col]) =
                        make_float2(acc[mt][t4][2] + b0, acc[mt][t4][3] + b1);
                }
            }
        } else {
#pragma unroll
            for (int t4 = 0; t4 < 4; t4++) {
                const int col = nt * 64 + warpn * 32 + t4 * 8 + qcol;
                const int t = (col >= 2 * CDIM) ? 2 : ((col >= CDIM) ? 1 : 0);
                const int rem = col - t * CDIM;
                const int hh = rem >> 5, dd = rem & 31;
                const float b0 = bias[col], b1 = bias[col + 1];
#pragma unroll
                for (int mt = 0; mt < 2; mt++) {
                    const int i0 = mt * 2, i1 = mt * 2 + 1;
                    const size_t o0 =
                        ((size_t)(rbi[i0] * HEADS + hh) * LTOK + rli[i0]) * HD + dd;
                    const size_t o1 =
                        ((size_t)(rbi[i1] * HEADS + hh) * LTOK + rli[i1]) * HD + dd;
                    float v00 = acc[mt][t4][0] + b0, v01 = acc[mt][t4][1] + b1;
                    float v10 = acc[mt][t4][2] + b0, v11 = acc[mt][t4][3] + b1;
                    if (t == 0) {
                        __half ha, la, hb, lb;
                        hsplit(v00 * QK_SCALE, ha, la); hsplit(v01 * QK_SCALE, hb, lb);
                        *reinterpret_cast<__half2*>(g_Qh + o0) = __halves2half2(ha, hb);
                        *reinterpret_cast<__half2*>(g_Ql + o0) = __halves2half2(la, lb);
                        hsplit(v10 * QK_SCALE, ha, la); hsplit(v11 * QK_SCALE, hb, lb);
                        *reinterpret_cast<__half2*>(g_Qh + o1) = __halves2half2(ha, hb);
                        *reinterpret_cast<__half2*>(g_Ql + o1) = __halves2half2(la, lb);
                    } else if (t == 1) {
                        *reinterpret_cast<__half2*>(g_Kh + o0) =
                            __floats2half2_rn(v00, v01);
                        *reinterpret_cast<__half2*>(g_Kh + o1) =
                            __floats2half2_rn(v10, v11);
                    } else {
                        __half ha, la, hb, lb;
                        hsplit(v00, ha, la); hsplit(v01, hb, lb);
                        *reinterpret_cast<__half2*>(g_Vh + o0) = __halves2half2(ha, hb);
                        *reinterpret_cast<__half2*>(g_Vl + o0) = __halves2half2(la, lb);
                        hsplit(v10, ha, la); hsplit(v11, hb, lb);
                        *reinterpret_cast<__half2*>(g_Vh + o1) = __halves2half2(ha, hb);
                        *reinterpret_cast<__half2*>(g_Vl + o1) = __halves2half2(la, lb);
                    }
                }
            }
        }
        __syncthreads();
    }
}

// ---------------------------------------------------------------------------
// K2: online-softmax mma attention. 288 thr, 2 CTA/SM, 3 chunks of 48 cols.
// ---------------------------------------------------------------------------
#define QSTR 40
#define VTSTR 152
#define ATTN_SMEM (3 * 144 * QSTR * 2 + 2 * 32 * VTSTR * 2)   // 54016 B

__global__ __launch_bounds__(288, 2) void attn_mma_kernel() {
    extern __shared__ __align__(16) char sraw[];
    __half* sQh = reinterpret_cast<__half*>(sraw);
    __half* sQl = sQh + 144 * QSTR;
    __half* sKh = sQl + 144 * QSTR;
    __half* sVh = sKh + 144 * QSTR;          // [32][VTSTR] transposed
    __half* sVl = sVh + 32 * VTSTR;

    const int bh = blockIdx.x;
    const int b = bh / HEADS, h = bh % HEADS;
    const int nw = b / WWINS;
    const int tid = threadIdx.x;
    const int warp = tid >> 5, lane = tid & 31;
    const size_t base = (size_t)bh * (LTOK * HD);

    for (int c = tid; c < 576; c += 288) {
        int l = c >> 2, dp = (c & 3) * 8;
        *reinterpret_cast<uint4*>(&sQh[l * QSTR + dp]) =
            *reinterpret_cast<const uint4*>(&g_Qh[base + l * 32 + dp]);
        *reinterpret_cast<uint4*>(&sQl[l * QSTR + dp]) =
            *reinterpret_cast<const uint4*>(&g_Ql[base + l * 32 + dp]);
        *reinterpret_cast<uint4*>(&sKh[l * QSTR + dp]) =
            *reinterpret_cast<const uint4*>(&g_Kh[base + l * 32 + dp]);
    }
    for (int i = tid; i < 2304; i += 288) {
        int l = i >> 4, d2 = (i & 15) * 2;
        __half2 vh = *reinterpret_cast<const __half2*>(&g_Vh[base + l * 32 + d2]);
        __half2 vl = *reinterpret_cast<const __half2*>(&g_Vl[base + l * 32 + d2]);
        sVh[d2 * VTSTR + l] = __low2half(vh);
        sVh[(d2 + 1) * VTSTR + l] = __high2half(vh);
        sVl[d2 * VTSTR + l] = __low2half(vl);
        sVl[(d2 + 1) * VTSTR + l] = __high2half(vl);
    }
    __syncthreads();

    const int lr = lane & 7, sel = lane >> 3;
    const int arow = lr + (sel & 1) * 8, acol = (sel >> 1) * 8;
    const int brow = lr + (sel >> 1) * 8, bcol = (sel & 1) * 8;
    const int g = lane >> 2, tg = lane & 3;

    uint32_t qh[2][4], ql[2][4];
#pragma unroll
    for (int ks = 0; ks < 2; ks++) {
        LDSM_X4(qh[ks][0], qh[ks][1], qh[ks][2], qh[ks][3],
                smem_u32(&sQh[(warp * 16 + arow) * QSTR + ks * 16 + acol]));
        LDSM_X4(ql[ks][0], ql[ks][1], ql[ks][2], ql[ks][3],
                smem_u32(&sQl[(warp * 16 + arow) * QSTR + ks * 16 + acol]));
    }

    const __half* biasrow = g_bias + (size_t)(nw * HEADS + h) * (LTOK * LTOK);
    const __half* maskrow = g_maskh + (size_t)b * (LTOK * LTOK);
    const int r0 = warp * 16 + g;
    const int r1 = r0 + 8;

    float m0 = -1e30f, m1 = -1e30f, s0 = 0.f, s1 = 0.f;
    float o[4][4];
#pragma unroll
    for (int nb = 0; nb < 4; nb++)
#pragma unroll
        for (int j = 0; j < 4; j++) o[nb][j] = 0.f;

#pragma unroll 1
    for (int ch = 0; ch < 3; ch++) {
        // ---- S chunk: cols [48ch, 48ch+48) ----
        float acc[6][4];
#pragma unroll
        for (int nb = 0; nb < 6; nb++)
#pragma unroll
            for (int j = 0; j < 4; j++) acc[nb][j] = 0.f;

#pragma unroll
        for (int j = 0; j < 3; j++) {
            const int nt = 3 * ch + j;
#pragma unroll
            for (int ks = 0; ks < 2; ks++) {
                uint32_t kh[4];
                LDSM_X4(kh[0], kh[1], kh[2], kh[3],
                        smem_u32(&sKh[(nt * 16 + brow) * QSTR + ks * 16 + bcol]));
                MMA_F16(acc[2 * j],     qh[ks], kh + 0);
                MMA_F16(acc[2 * j + 1], qh[ks], kh + 2);
                MMA_F16(acc[2 * j],     ql[ks], kh + 0);
                MMA_F16(acc[2 * j + 1], ql[ks], kh + 2);
            }
        }

        // ---- bias + mask ----
#pragma unroll
        for (int nb = 0; nb < 6; nb++) {
            const int cc = 48 * ch + nb * 8 + tg * 2;
            float2 b0 = __half22float2(
                *reinterpret_cast<const __half2*>(&biasrow[r0 * LTOK + cc]));
            float2 m0v = __half22float2(
                *reinterpret_cast<const __half2*>(&maskrow[r0 * LTOK + cc]));
            float2 b1 = __half22float2(
                *reinterpret_cast<const __half2*>(&biasrow[r1 * LTOK + cc]));
            float2 m1v = __half22float2(
                *reinterpret_cast<const __half2*>(&maskrow[r1 * LTOK + cc]));
            acc[nb][0] += b0.x + m0v.x;
            acc[nb][1] += b0.y + m0v.y;
            acc[nb][2] += b1.x + m1v.x;
            acc[nb][3] += b1.y + m1v.y;
        }

        // ---- chunk max, rescale running state ----
        float cm0 = -1e30f, cm1 = -1e30f;
#pragma unroll
        for (int nb = 0; nb < 6; nb++) {
            cm0 = fmaxf(cm0, fmaxf(acc[nb][0], acc[nb][1]));
            cm1 = fmaxf(cm1, fmaxf(acc[nb][2], acc[nb][3]));
        }
        cm0 = fmaxf(cm0, __shfl_xor_sync(0xffffffffu, cm0, 1));
        cm0 = fmaxf(cm0, __shfl_xor_sync(0xffffffffu, cm0, 2));
        cm1 = fmaxf(cm1, __shfl_xor_sync(0xffffffffu, cm1, 1));
        cm1 = fmaxf(cm1, __shfl_xor_sync(0xffffffffu, cm1, 2));
        const float nm0 = fmaxf(m0, cm0);
        const float nm1 = fmaxf(m1, cm1);
        const float sc0 = fexp(m0 - nm0);
        const float sc1 = fexp(m1 - nm1);
        m0 = nm0; m1 = nm1;
        s0 *= sc0; s1 *= sc1;
#pragma unroll
        for (int nb = 0; nb < 4; nb++) {
            o[nb][0] *= sc0; o[nb][1] *= sc0;
            o[nb][2] *= sc1; o[nb][3] *= sc1;
        }

        // ---- exp + accumulate sums ----
#pragma unroll
        for (int nb = 0; nb < 6; nb++) {
            acc[nb][0] = fexp(acc[nb][0] - nm0);
            acc[nb][1] = fexp(acc[nb][1] - nm0);
            acc[nb][2] = fexp(acc[nb][2] - nm1);
            acc[nb][3] = fexp(acc[nb][3] - nm1);
            s0 += acc[nb][0] + acc[nb][1];
            s1 += acc[nb][2] + acc[nb][3];
        }

        // ---- PV chunk (unnormalized P) ----
#pragma unroll
        for (int k = 0; k < 3; k++) {
            const int ksg = 3 * ch + k;
            uint32_t a[4];
            a[0] = pack_h2(acc[2 * k][0], acc[2 * k][1]);
            a[1] = pack_h2(acc[2 * k][2], acc[2 * k][3]);
            a[2] = pack_h2(acc[2 * k + 1][0], acc[2 * k + 1][1]);
            a[3] = pack_h2(acc[2 * k + 1][2], acc[2 * k + 1][3]);
#pragma unroll
            for (int ntv = 0; ntv < 2; ntv++) {
                uint32_t vh[4], vl[4];
                LDSM_X4(vh[0], vh[1], vh[2], vh[3],
                        smem_u32(&sVh[(ntv * 16 + brow) * VTSTR + ksg * 16 + bcol]));
                LDSM_X4(vl[0], vl[1], vl[2], vl[3],
                        smem_u32(&sVl[(ntv * 16 + brow) * VTSTR + ksg * 16 + bcol]));
                MMA_F16(o[2 * ntv],     a, vh + 0);
                MMA_F16(o[2 * ntv + 1], a, vh + 2);
                MMA_F16(o[2 * ntv],     a, vl + 0);
                MMA_F16(o[2 * ntv + 1], a, vl + 2);
            }
        }
    }

    // ---- final normalization ----
    s0 += __shfl_xor_sync(0xffffffffu, s0, 1);
    s0 += __shfl_xor_sync(0xffffffffu, s0, 2);
    s1 += __shfl_xor_sync(0xffffffffu, s1, 1);
    s1 += __shfl_xor_sync(0xffffffffu, s1, 2);
    const float inv0 = 1.f / s0, inv1 = 1.f / s1;

#pragma unroll
    for (int nb = 0; nb < 4; nb++) {
        const int d0 = nb * 8 + tg * 2;
        const size_t off0 = ((size_t)b * LTOK + r0) * CDIM + h * HD + d0;
        const size_t off1 = ((size_t)b * LTOK + r1) * CDIM + h * HD + d0;
        *reinterpret_cast<__half2*>(&g_ctx[off0]) =
            __floats2half2_rn(o[nb][0] * inv0, o[nb][1] * inv0);
        *reinterpret_cast<__half2*>(&g_ctx[off1]) =
            __floats2half2_rn(o[nb][2] * inv1, o[nb][3] * inv1);
    }
}

// ---------------------------------------------------------------------------
extern "C" void kernel_launch(void* const* d_in, const int* in_sizes, int n_in,
                              void* d_out, int out_size) {
    const float* x    = (const float*)d_in[0];
    const float* mask = (const float*)d_in[1];
    const float* W1   = (const float*)d_in[2];
    const float* b1   = (const float*)d_in[3];
    const float* W2   = (const float*)d_in[4];
    const float* b2   = (const float*)d_in[5];
    const float* btab = (const float*)d_in[6];
    const int*   pidx = (const int*)d_in[7];
    float* out = (float*)d_out;
    (void)in_sizes; (void)n_in; (void)out_size;

    cudaFuncSetAttribute(mma_gemm_kernel,
                         cudaFuncAttributeMaxDynamicSharedMemorySize, GEMM_SMEM);
    cudaFuncSetAttribute(attn_mma_kernel,
                         cudaFuncAttributeMaxDynamicSharedMemorySize, ATTN_SMEM);

    __half *w1h, *w1l, *w2h, *w2l, *ctx;
    cudaGetSymbolAddress((void**)&w1h, g_W1h);
    cudaGetSymbolAddress((void**)&w1l, g_W1l);
    cudaGetSymbolAddress((void**)&w2h, g_W2h);
    cudaGetSymbolAddress((void**)&w2l, g_W2l);
    cudaGetSymbolAddress((void**)&ctx, g_ctx);

    splitW_kernel<<<(576 * 192 + 255) / 256, 256>>>(W1, w1h, w1l, 576);
    splitW_kernel<<<(192 * 192 + 255) / 256, 256>>>(W2, w2h, w2l, 192);
    mask2h_kernel<<<(NWIN * LTOK * LTOK / 4 + 255) / 256, 256>>>(mask,
                                                                 NWIN * LTOK * LTOK / 4);
    bias_gather_kernel<<<NW * 8, 256>>>(btab, pidx);

    mma_gemm_kernel<<<MTOT / 128, 256, GEMM_SMEM>>>(x, w1h, w1l, b1, 9, 0, nullptr);
    attn_mma_kernel<<<NWIN * HEADS, 288, ATTN_SMEM>>>();
    mma_gemm_kernel<<<MTOT / 128, 256, GEMM_SMEM>>>(ctx, w2h, w2l, b2, 3, 1, out);
}

// round 11
// speedup vs baseline: 1.2725x; 1.0528x over previous
#include <cuda_runtime.h>
#include <cuda_bf16.h>
#include <cuda_fp16.h>
#include <cstdint>

// ---------------------------------------------------------------------------
// EarthAttention3D: B_=960, L=144, C=192, H=6, hd=32, NUM_WINDOWS=64, W_WINS=15
// Round 11: cp.async-pipelined GEMM (B[nt+1] load hidden under epilogue(nt)),
// fp32 mask read directly (mask2h deleted), vectorized bias gather.
// ---------------------------------------------------------------------------

#define NWIN   960
#define LTOK   144
#define CDIM   192
#define HEADS  6
#define HD     32
#define NW     64
#define WWINS  15
#define MTOT   (NWIN * LTOK)          // 138240
#define QK_SCALE 0.17677669529663687f

// ------------------------- scratch (device globals) ------------------------
__device__ __half g_bias[NW * HEADS * LTOK * LTOK];
__device__ __half g_ctx[MTOT * CDIM];
__device__ __half g_Qh[NWIN * HEADS * LTOK * HD];
__device__ __half g_Ql[NWIN * HEADS * LTOK * HD];
__device__ __half g_Kh[NWIN * HEADS * LTOK * HD];
__device__ __half g_Vh[NWIN * HEADS * LTOK * HD];
__device__ __half g_Vl[NWIN * HEADS * LTOK * HD];
__device__ __half g_W1h[576 * 192];
__device__ __half g_W1l[576 * 192];
__device__ __half g_W2h[192 * 192];
__device__ __half g_W2l[192 * 192];

// ------------------------------ helpers ------------------------------------
__device__ __forceinline__ uint32_t smem_u32(const void* p) {
    uint32_t a;
    asm("{ .reg .u64 t; cvta.to.shared.u64 t, %1; cvt.u32.u64 %0, t; }"
        : "=r"(a) : "l"(p));
    return a;
}
__device__ __forceinline__ void hsplit(float v, __half& h, __half& l) {
    h = __float2half_rn(v);
    l = __float2half_rn(v - __half2float(h));
}
__device__ __forceinline__ uint32_t pack_h2(float a, float b) {
    __half2 t = __floats2half2_rn(a, b);
    return *reinterpret_cast<uint32_t*>(&t);
}
// exp(x) on the FMA pipe
__device__ __forceinline__ float fexp(float x) {
    float y = fmaxf(x * 1.4426950408889634f, -126.0f);
    float n = rintf(y);
    float f = y - n;
    float p = 0.0013333558f;
    p = fmaf(p, f, 0.009618129f);
    p = fmaf(p, f, 0.055504109f);
    p = fmaf(p, f, 0.24022651f);
    p = fmaf(p, f, 0.69314718f);
    p = fmaf(p, f, 1.0f);
    return __int_as_float(((int)n + 127) << 23) * p;
}

#define LDSM_X4(r0, r1, r2, r3, addr)                                          \
    asm volatile("ldmatrix.sync.aligned.m8n8.x4.shared.b16 {%0,%1,%2,%3}, [%4];" \
                 : "=r"(r0), "=r"(r1), "=r"(r2), "=r"(r3) : "r"(addr))

#define MMA_F16(d, a, b)                                                       \
    asm volatile("mma.sync.aligned.m16n8k16.row.col.f32.f16.f16.f32 "          \
                 "{%0,%1,%2,%3}, {%4,%5,%6,%7}, {%8,%9}, {%0,%1,%2,%3};"       \
                 : "+f"((d)[0]), "+f"((d)[1]), "+f"((d)[2]), "+f"((d)[3])      \
                 : "r"((a)[0]), "r"((a)[1]), "r"((a)[2]), "r"((a)[3]),         \
                   "r"((b)[0]), "r"((b)[1]))

#define CP_ASYNC16(sm, gm)                                                     \
    asm volatile("cp.async.cg.shared.global [%0], [%1], 16;"                   \
                 :: "r"(sm), "l"(gm) : "memory")
#define CP_COMMIT() asm volatile("cp.async.commit_group;" ::: "memory")
#define CP_WAIT0()  asm volatile("cp.async.wait_group 0;" ::: "memory")

// ---------------------------------------------------------------------------
// Prep: W [192][N] fp32 -> [N][192] fp16 hi/lo (transposed)
// ---------------------------------------------------------------------------
__global__ void splitW_kernel(const float* __restrict__ W,
                              __half* __restrict__ h, __half* __restrict__ l,
                              int N) {
    int idx = blockIdx.x * blockDim.x + threadIdx.x;
    if (idx >= N * 192) return;
    int n = idx / 192, k = idx - n * 192;
    __half hh, ll;
    hsplit(W[(size_t)k * N + n], hh, ll);
    h[idx] = hh; l[idx] = ll;
}

// ---------------------------------------------------------------------------
// K0: bias gather (fp16 out), 16x split, float2-vectorized table reads
// ---------------------------------------------------------------------------
__global__ void bias_gather_kernel(const float* __restrict__ table,
                                   const int* __restrict__ pidx) {
    const int nw = blockIdx.x >> 4;
    const int part = blockIdx.x & 15;
    const size_t dbase = (size_t)nw * HEADS * (LTOK * LTOK);
    for (int i = part * 1296 + threadIdx.x; i < (part + 1) * 1296; i += 256) {
        const int pi = pidx[i];
        const float2* src = reinterpret_cast<const float2*>(
            table + (size_t)pi * (NW * HEADS) + nw * HEADS);
        float2 a = src[0], b = src[1], c = src[2];
        g_bias[dbase + 0 * (LTOK * LTOK) + i] = __float2half_rn(a.x);
        g_bias[dbase + 1 * (LTOK * LTOK) + i] = __float2half_rn(a.y);
        g_bias[dbase + 2 * (LTOK * LTOK) + i] = __float2half_rn(b.x);
        g_bias[dbase + 3 * (LTOK * LTOK) + i] = __float2half_rn(b.y);
        g_bias[dbase + 4 * (LTOK * LTOK) + i] = __float2half_rn(c.x);
        g_bias[dbase + 5 * (LTOK * LTOK) + i] = __float2half_rn(c.y);
    }
}

// ---------------------------------------------------------------------------
// fp16 2-pass GEMM (B split), cp.async pipelined: B[nt+1] hidden under
// epilogue(nt). mode 0: A fp32 -> scatter Q/K/V; mode 1: A fp16 -> out fp32.
// ---------------------------------------------------------------------------
#define ASTR 200
#define GEMM_SMEM ((128 * ASTR + 2 * 64 * ASTR) * 2)  // 102400 B

__global__ __launch_bounds__(256, 2) void mma_gemm_kernel(
    const void* __restrict__ Ain, const __half* __restrict__ Bh,
    const __half* __restrict__ Bl, const float* __restrict__ bias,
    int ntiles, int mode, float* __restrict__ out) {
    extern __shared__ __align__(16) __half sb[];
    __half* sA  = sb;                      // [128][ASTR]
    __half* sBh = sb + 128 * ASTR;         // [64][ASTR]
    __half* sBl = sBh + 64 * ASTR;

    const int tid = threadIdx.x;
    const int warp = tid >> 5, lane = tid & 31;
    const int warpm = warp >> 1, warpn = warp & 1;
    const int m_blk = blockIdx.x * 128;

    // per-thread B-load coordinates (6 chunks of uint4 each for hi and lo)
    const int br_ = tid / 24 + 0;          // unused placeholder to keep regs low
    (void)br_;

    // ---- issue B tile 0 loads (async) ----
    {
#pragma unroll
        for (int it = 0; it < 6; it++) {
            int i = tid + it * 256;
            int r = i / 24, c = (i % 24) * 8;
            CP_ASYNC16(smem_u32(&sBh[r * ASTR + c]),
                       (const void*)&Bh[(size_t)r * 192 + c]);
            CP_ASYNC16(smem_u32(&sBl[r * ASTR + c]),
                       (const void*)&Bl[(size_t)r * 192 + c]);
        }
        CP_COMMIT();
    }

    // ---- stage A ----
    if (mode == 1) {
        const __half* A = (const __half*)Ain;
        for (int i = tid; i < 128 * 24; i += 256) {
            int r = i / 24, c = (i % 24) * 8;
            *reinterpret_cast<uint4*>(&sA[r * ASTR + c]) =
                *reinterpret_cast<const uint4*>(&A[(size_t)(m_blk + r) * 192 + c]);
        }
    } else {
        const float* A = (const float*)Ain;
        for (int i = tid; i < 128 * 48; i += 256) {
            int r = i / 48, c4 = (i % 48) * 4;
            float4 v = *reinterpret_cast<const float4*>(&A[(size_t)(m_blk + r) * 192 + c4]);
            *reinterpret_cast<__half2*>(&sA[r * ASTR + c4]) = __floats2half2_rn(v.x, v.y);
            *reinterpret_cast<__half2*>(&sA[r * ASTR + c4 + 2]) = __floats2half2_rn(v.z, v.w);
        }
    }
    CP_WAIT0();
    __syncthreads();

    const int lr = lane & 7, sel = lane >> 3;
    const int a_row_off = lr + (sel & 1) * 8;
    const int a_col_off = (sel >> 1) * 8;
    const int b_row_off = lr + (sel >> 1) * 8;
    const int b_col_off = (sel & 1) * 8;
    const int qrow = lane >> 2;
    const int qcol = (lane & 3) * 2;

    int rbi[4], rli[4];
#pragma unroll
    for (int i = 0; i < 4; i++) {
        int r = m_blk + warpm * 32 + (i >> 1) * 16 + (i & 1) * 8 + qrow;
        rbi[i] = r / LTOK;
        rli[i] = r - rbi[i] * LTOK;
    }

    for (int nt = 0; nt < ntiles; nt++) {
        float acc[2][4][4];
#pragma unroll
        for (int mt = 0; mt < 2; mt++)
#pragma unroll
            for (int t4 = 0; t4 < 4; t4++)
#pragma unroll
                for (int j = 0; j < 4; j++) acc[mt][t4][j] = 0.f;

#pragma unroll 4
        for (int ks = 0; ks < 12; ks++) {
            const int k0 = ks * 16;
            uint32_t a[2][4], bh[4][2], bl[4][2];
#pragma unroll
            for (int mt = 0; mt < 2; mt++) {
                int row = warpm * 32 + mt * 16 + a_row_off;
                LDSM_X4(a[mt][0], a[mt][1], a[mt][2], a[mt][3],
                        smem_u32(&sA[row * ASTR + k0 + a_col_off]));
            }
#pragma unroll
            for (int pr = 0; pr < 2; pr++) {
                int row = warpn * 32 + pr * 16 + b_row_off;
                LDSM_X4(bh[2 * pr][0], bh[2 * pr][1], bh[2 * pr + 1][0],
                        bh[2 * pr + 1][1],
                        smem_u32(&sBh[row * ASTR + k0 + b_col_off]));
                LDSM_X4(bl[2 * pr][0], bl[2 * pr][1], bl[2 * pr + 1][0],
                        bl[2 * pr + 1][1],
                        smem_u32(&sBl[row * ASTR + k0 + b_col_off]));
            }
#pragma unroll
            for (int mt = 0; mt < 2; mt++)
#pragma unroll
                for (int t4 = 0; t4 < 4; t4++) {
                    MMA_F16(acc[mt][t4], a[mt], bh[t4]);
                    MMA_F16(acc[mt][t4], a[mt], bl[t4]);
                }
        }
        __syncthreads();  // all warps done reading sB

        // ---- issue next B tile loads (hidden under epilogue) ----
        if (nt + 1 < ntiles) {
            const size_t nb = (size_t)(nt + 1) * 64;
#pragma unroll
            for (int it = 0; it < 6; it++) {
                int i = tid + it * 256;
                int r = i / 24, c = (i % 24) * 8;
                CP_ASYNC16(smem_u32(&sBh[r * ASTR + c]),
                           (const void*)&Bh[(nb + r) * 192 + c]);
                CP_ASYNC16(smem_u32(&sBl[r * ASTR + c]),
                           (const void*)&Bl[(nb + r) * 192 + c]);
            }
            CP_COMMIT();
        }

        // ---- epilogue(nt) ----
        if (mode == 1) {
#pragma unroll
            for (int t4 = 0; t4 < 4; t4++) {
                const int col = nt * 64 + warpn * 32 + t4 * 8 + qcol;
                const float b0 = bias[col], b1 = bias[col + 1];
#pragma unroll
                for (int mt = 0; mt < 2; mt++) {
                    const int r0 = m_blk + warpm * 32 + mt * 16 + qrow;
                    *reinterpret_cast<float2*>(&out[(size_t)r0 * CDIM + col]) =
                        make_float2(acc[mt][t4][0] + b0, acc[mt][t4][1] + b1);
                    *reinterpret_cast<float2*>(&out[(size_t)(r0 + 8) * CDIM + col]) =
                        make_float2(acc[mt][t4][2] + b0, acc[mt][t4][3] + b1);
                }
            }
        } else {
#pragma unroll
            for (int t4 = 0; t4 < 4; t4++) {
                const int col = nt * 64 + warpn * 32 + t4 * 8 + qcol;
                const int t = (col >= 2 * CDIM) ? 2 : ((col >= CDIM) ? 1 : 0);
                const int rem = col - t * CDIM;
                const int hh = rem >> 5, dd = rem & 31;
                const float b0 = bias[col], b1 = bias[col + 1];
#pragma unroll
                for (int mt = 0; mt < 2; mt++) {
                    const int i0 = mt * 2, i1 = mt * 2 + 1;
                    const size_t o0 =
                        ((size_t)(rbi[i0] * HEADS + hh) * LTOK + rli[i0]) * HD + dd;
                    const size_t o1 =
                        ((size_t)(rbi[i1] * HEADS + hh) * LTOK + rli[i1]) * HD + dd;
                    float v00 = acc[mt][t4][0] + b0, v01 = acc[mt][t4][1] + b1;
                    float v10 = acc[mt][t4][2] + b0, v11 = acc[mt][t4][3] + b1;
                    if (t == 0) {
                        __half ha, la, hb, lb;
                        hsplit(v00 * QK_SCALE, ha, la); hsplit(v01 * QK_SCALE, hb, lb);
                        *reinterpret_cast<__half2*>(g_Qh + o0) = __halves2half2(ha, hb);
                        *reinterpret_cast<__half2*>(g_Ql + o0) = __halves2half2(la, lb);
                        hsplit(v10 * QK_SCALE, ha, la); hsplit(v11 * QK_SCALE, hb, lb);
                        *reinterpret_cast<__half2*>(g_Qh + o1) = __halves2half2(ha, hb);
                        *reinterpret_cast<__half2*>(g_Ql + o1) = __halves2half2(la, lb);
                    } else if (t == 1) {
                        *reinterpret_cast<__half2*>(g_Kh + o0) =
                            __floats2half2_rn(v00, v01);
                        *reinterpret_cast<__half2*>(g_Kh + o1) =
                            __floats2half2_rn(v10, v11);
                    } else {
                        __half ha, la, hb, lb;
                        hsplit(v00, ha, la); hsplit(v01, hb, lb);
                        *reinterpret_cast<__half2*>(g_Vh + o0) = __halves2half2(ha, hb);
                        *reinterpret_cast<__half2*>(g_Vl + o0) = __halves2half2(la, lb);
                        hsplit(v10, ha, la); hsplit(v11, hb, lb);
                        *reinterpret_cast<__half2*>(g_Vh + o1) = __halves2half2(ha, hb);
                        *reinterpret_cast<__half2*>(g_Vl + o1) = __halves2half2(la, lb);
                    }
                }
            }
        }
        if (nt + 1 < ntiles) CP_WAIT0();
        __syncthreads();
    }
}

// ---------------------------------------------------------------------------
// K2: online-softmax mma attention. 288 thr, 2 CTA/SM, 3 chunks of 48 cols.
// Mask read directly as fp32.
// ---------------------------------------------------------------------------
#define QSTR 40
#define VTSTR 152
#define ATTN_SMEM (3 * 144 * QSTR * 2 + 2 * 32 * VTSTR * 2)   // 54016 B

__global__ __launch_bounds__(288, 2) void attn_mma_kernel(const float* __restrict__ mask) {
    extern __shared__ __align__(16) char sraw[];
    __half* sQh = reinterpret_cast<__half*>(sraw);
    __half* sQl = sQh + 144 * QSTR;
    __half* sKh = sQl + 144 * QSTR;
    __half* sVh = sKh + 144 * QSTR;          // [32][VTSTR] transposed
    __half* sVl = sVh + 32 * VTSTR;

    const int bh = blockIdx.x;
    const int b = bh / HEADS, h = bh % HEADS;
    const int nw = b / WWINS;
    const int tid = threadIdx.x;
    const int warp = tid >> 5, lane = tid & 31;
    const size_t base = (size_t)bh * (LTOK * HD);

    for (int c = tid; c < 576; c += 288) {
        int l = c >> 2, dp = (c & 3) * 8;
        *reinterpret_cast<uint4*>(&sQh[l * QSTR + dp]) =
            *reinterpret_cast<const uint4*>(&g_Qh[base + l * 32 + dp]);
        *reinterpret_cast<uint4*>(&sQl[l * QSTR + dp]) =
            *reinterpret_cast<const uint4*>(&g_Ql[base + l * 32 + dp]);
        *reinterpret_cast<uint4*>(&sKh[l * QSTR + dp]) =
            *reinterpret_cast<const uint4*>(&g_Kh[base + l * 32 + dp]);
    }
    for (int i = tid; i < 2304; i += 288) {
        int l = i >> 4, d2 = (i & 15) * 2;
        __half2 vh = *reinterpret_cast<const __half2*>(&g_Vh[base + l * 32 + d2]);
        __half2 vl = *reinterpret_cast<const __half2*>(&g_Vl[base + l * 32 + d2]);
        sVh[d2 * VTSTR + l] = __low2half(vh);
        sVh[(d2 + 1) * VTSTR + l] = __high2half(vh);
        sVl[d2 * VTSTR + l] = __low2half(vl);
        sVl[(d2 + 1) * VTSTR + l] = __high2half(vl);
    }
    __syncthreads();

    const int lr = lane & 7, sel = lane >> 3;
    const int arow = lr + (sel & 1) * 8, acol = (sel >> 1) * 8;
    const int brow = lr + (sel >> 1) * 8, bcol = (sel & 1) * 8;
    const int g = lane >> 2, tg = lane & 3;

    uint32_t qh[2][4], ql[2][4];
#pragma unroll
    for (int ks = 0; ks < 2; ks++) {
        LDSM_X4(qh[ks][0], qh[ks][1], qh[ks][2], qh[ks][3],
                smem_u32(&sQh[(warp * 16 + arow) * QSTR + ks * 16 + acol]));
        LDSM_X4(ql[ks][0], ql[ks][1], ql[ks][2], ql[ks][3],
                smem_u32(&sQl[(warp * 16 + arow) * QSTR + ks * 16 + acol]));
    }

    const __half* biasrow = g_bias + (size_t)(nw * HEADS + h) * (LTOK * LTOK);
    const float* maskrow = mask + (size_t)b * (LTOK * LTOK);
    const int r0 = warp * 16 + g;
    const int r1 = r0 + 8;

    float m0 = -1e30f, m1 = -1e30f, s0 = 0.f, s1 = 0.f;
    float o[4][4];
#pragma unroll
    for (int nb = 0; nb < 4; nb++)
#pragma unroll
        for (int j = 0; j < 4; j++) o[nb][j] = 0.f;

#pragma unroll 1
    for (int ch = 0; ch < 3; ch++) {
        float acc[6][4];
#pragma unroll
        for (int nb = 0; nb < 6; nb++)
#pragma unroll
            for (int j = 0; j < 4; j++) acc[nb][j] = 0.f;

#pragma unroll
        for (int j = 0; j < 3; j++) {
            const int nt = 3 * ch + j;
#pragma unroll
            for (int ks = 0; ks < 2; ks++) {
                uint32_t kh[4];
                LDSM_X4(kh[0], kh[1], kh[2], kh[3],
                        smem_u32(&sKh[(nt * 16 + brow) * QSTR + ks * 16 + bcol]));
                MMA_F16(acc[2 * j],     qh[ks], kh + 0);
                MMA_F16(acc[2 * j + 1], qh[ks], kh + 2);
                MMA_F16(acc[2 * j],     ql[ks], kh + 0);
                MMA_F16(acc[2 * j + 1], ql[ks], kh + 2);
            }
        }

#pragma unroll
        for (int nb = 0; nb < 6; nb++) {
            const int cc = 48 * ch + nb * 8 + tg * 2;
            float2 b0 = __half22float2(
                *reinterpret_cast<const __half2*>(&biasrow[r0 * LTOK + cc]));
            float2 m0v = *reinterpret_cast<const float2*>(&maskrow[r0 * LTOK + cc]);
            float2 b1 = __half22float2(
                *reinterpret_cast<const __half2*>(&biasrow[r1 * LTOK + cc]));
            float2 m1v = *reinterpret_cast<const float2*>(&maskrow[r1 * LTOK + cc]);
            acc[nb][0] += b0.x + m0v.x;
            acc[nb][1] += b0.y + m0v.y;
            acc[nb][2] += b1.x + m1v.x;
            acc[nb][3] += b1.y + m1v.y;
        }

        float cm0 = -1e30f, cm1 = -1e30f;
#pragma unroll
        for (int nb = 0; nb < 6; nb++) {
            cm0 = fmaxf(cm0, fmaxf(acc[nb][0], acc[nb][1]));
            cm1 = fmaxf(cm1, fmaxf(acc[nb][2], acc[nb][3]));
        }
        cm0 = fmaxf(cm0, __shfl_xor_sync(0xffffffffu, cm0, 1));
        cm0 = fmaxf(cm0, __shfl_xor_sync(0xffffffffu, cm0, 2));
        cm1 = fmaxf(cm1, __shfl_xor_sync(0xffffffffu, cm1, 1));
        cm1 = fmaxf(cm1, __shfl_xor_sync(0xffffffffu, cm1, 2));
        const float nm0 = fmaxf(m0, cm0);
        const float nm1 = fmaxf(m1, cm1);
        const float sc0 = fexp(m0 - nm0);
        const float sc1 = fexp(m1 - nm1);
        m0 = nm0; m1 = nm1;
        s0 *= sc0; s1 *= sc1;
#pragma unroll
        for (int nb = 0; nb < 4; nb++) {
            o[nb][0] *= sc0; o[nb][1] *= sc0;
            o[nb][2] *= sc1; o[nb][3] *= sc1;
        }

#pragma unroll
        for (int nb = 0; nb < 6; nb++) {
            acc[nb][0] = fexp(acc[nb][0] - nm0);
            acc[nb][1] = fexp(acc[nb][1] - nm0);
            acc[nb][2] = fexp(acc[nb][2] - nm1);
            acc[nb][3] = fexp(acc[nb][3] - nm1);
            s0 += acc[nb][0] + acc[nb][1];
            s1 += acc[nb][2] + acc[nb][3];
        }

#pragma unroll
        for (int k = 0; k < 3; k++) {
            const int ksg = 3 * ch + k;
            uint32_t a[4];
            a[0] = pack_h2(acc[2 * k][0], acc[2 * k][1]);
            a[1] = pack_h2(acc[2 * k][2], acc[2 * k][3]);
            a[2] = pack_h2(acc[2 * k + 1][0], acc[2 * k + 1][1]);
            a[3] = pack_h2(acc[2 * k + 1][2], acc[2 * k + 1][3]);
#pragma unroll
            for (int ntv = 0; ntv < 2; ntv++) {
                uint32_t vh[4], vl[4];
                LDSM_X4(vh[0], vh[1], vh[2], vh[3],
                        smem_u32(&sVh[(ntv * 16 + brow) * VTSTR + ksg * 16 + bcol]));
                LDSM_X4(vl[0], vl[1], vl[2], vl[3],
                        smem_u32(&sVl[(ntv * 16 + brow) * VTSTR + ksg * 16 + bcol]));
                MMA_F16(o[2 * ntv],     a, vh + 0);
                MMA_F16(o[2 * ntv + 1], a, vh + 2);
                MMA_F16(o[2 * ntv],     a, vl + 0);
                MMA_F16(o[2 * ntv + 1], a, vl + 2);
            }
        }
    }

    s0 += __shfl_xor_sync(0xffffffffu, s0, 1);
    s0 += __shfl_xor_sync(0xffffffffu, s0, 2);
    s1 += __shfl_xor_sync(0xffffffffu, s1, 1);
    s1 += __shfl_xor_sync(0xffffffffu, s1, 2);
    const float inv0 = 1.f / s0, inv1 = 1.f / s1;

#pragma unroll
    for (int nb = 0; nb < 4; nb++) {
        const int d0 = nb * 8 + tg * 2;
        const size_t off0 = ((size_t)b * LTOK + r0) * CDIM + h * HD + d0;
        const size_t off1 = ((size_t)b * LTOK + r1) * CDIM + h * HD + d0;
        *reinterpret_cast<__half2*>(&g_ctx[off0]) =
            __floats2half2_rn(o[nb][0] * inv0, o[nb][1] * inv0);
        *reinterpret_cast<__half2*>(&g_ctx[off1]) =
            __floats2half2_rn(o[nb][2] * inv1, o[nb][3] * inv1);
    }
}

// ---------------------------------------------------------------------------
extern "C" void kernel_launch(void* const* d_in, const int* in_sizes, int n_in,
                              void* d_out, int out_size) {
    const float* x    = (const float*)d_in[0];
    const float* mask = (const float*)d_in[1];
    const float* W1   = (const float*)d_in[2];
    const float* b1   = (const float*)d_in[3];
    const float* W2   = (const float*)d_in[4];
    const float* b2   = (const float*)d_in[5];
    const float* btab = (const float*)d_in[6];
    const int*   pidx = (const int*)d_in[7];
    float* out = (float*)d_out;
    (void)in_sizes; (void)n_in; (void)out_size;

    cudaFuncSetAttribute(mma_gemm_kernel,
                         cudaFuncAttributeMaxDynamicSharedMemorySize, GEMM_SMEM);
    cudaFuncSetAttribute(attn_mma_kernel,
                         cudaFuncAttributeMaxDynamicSharedMemorySize, ATTN_SMEM);

    __half *w1h, *w1l, *w2h, *w2l, *ctx;
    cudaGetSymbolAddress((void**)&w1h, g_W1h);
    cudaGetSymbolAddress((void**)&w1l, g_W1l);
    cudaGetSymbolAddress((void**)&w2h, g_W2h);
    cudaGetSymbolAddress((void**)&w2l, g_W2l);
    cudaGetSymbolAddress((void**)&ctx, g_ctx);

    splitW_kernel<<<(576 * 192 + 255) / 256, 256>>>(W1, w1h, w1l, 576);
    splitW_kernel<<<(192 * 192 + 255) / 256, 256>>>(W2, w2h, w2l, 192);
    bias_gather_kernel<<<NW * 16, 256>>>(btab, pidx);

    mma_gemm_kernel<<<MTOT / 128, 256, GEMM_SMEM>>>(x, w1h, w1l, b1, 9, 0, nullptr);
    attn_mma_kernel<<<NWIN * HEADS, 288, ATTN_SMEM>>>(mask);
    mma_gemm_kernel<<<MTOT / 128, 256, GEMM_SMEM>>>(ctx, w2h, w2l, b2, 3, 1, out);
}

// round 12
// speedup vs baseline: 1.4684x; 1.1540x over previous
#include <cuda_runtime.h>
#include <cuda_bf16.h>
#include <cuda_fp16.h>
#include <cstdint>

// ---------------------------------------------------------------------------
// EarthAttention3D: B_=960, L=144, C=192, H=6, hd=32, NUM_WINDOWS=64, W_WINS=15
// Round 12: pass elimination by error budget — QKV GEMM single-pass (fp16),
// attention S = Qh@Kh only; out-proj stays 2-pass; PV keeps Vh+Vl.
// ---------------------------------------------------------------------------

#define NWIN   960
#define LTOK   144
#define CDIM   192
#define HEADS  6
#define HD     32
#define NW     64
#define WWINS  15
#define MTOT   (NWIN * LTOK)          // 138240
#define QK_SCALE 0.17677669529663687f

// ------------------------- scratch (device globals) ------------------------
__device__ __half g_bias[NW * HEADS * LTOK * LTOK];
__device__ __half g_ctx[MTOT * CDIM];
__device__ __half g_Qh[NWIN * HEADS * LTOK * HD];
__device__ __half g_Kh[NWIN * HEADS * LTOK * HD];
__device__ __half g_Vh[NWIN * HEADS * LTOK * HD];
__device__ __half g_Vl[NWIN * HEADS * LTOK * HD];
__device__ __half g_W1h[576 * 192];
__device__ __half g_W2h[192 * 192];
__device__ __half g_W2l[192 * 192];

// ------------------------------ helpers ------------------------------------
__device__ __forceinline__ uint32_t smem_u32(const void* p) {
    uint32_t a;
    asm("{ .reg .u64 t; cvta.to.shared.u64 t, %1; cvt.u32.u64 %0, t; }"
        : "=r"(a) : "l"(p));
    return a;
}
__device__ __forceinline__ void hsplit(float v, __half& h, __half& l) {
    h = __float2half_rn(v);
    l = __float2half_rn(v - __half2float(h));
}
__device__ __forceinline__ uint32_t pack_h2(float a, float b) {
    __half2 t = __floats2half2_rn(a, b);
    return *reinterpret_cast<uint32_t*>(&t);
}
// exp(x) on the FMA pipe
__device__ __forceinline__ float fexp(float x) {
    float y = fmaxf(x * 1.4426950408889634f, -126.0f);
    float n = rintf(y);
    float f = y - n;
    float p = 0.0013333558f;
    p = fmaf(p, f, 0.009618129f);
    p = fmaf(p, f, 0.055504109f);
    p = fmaf(p, f, 0.24022651f);
    p = fmaf(p, f, 0.69314718f);
    p = fmaf(p, f, 1.0f);
    return __int_as_float(((int)n + 127) << 23) * p;
}

#define LDSM_X4(r0, r1, r2, r3, addr)                                          \
    asm volatile("ldmatrix.sync.aligned.m8n8.x4.shared.b16 {%0,%1,%2,%3}, [%4];" \
                 : "=r"(r0), "=r"(r1), "=r"(r2), "=r"(r3) : "r"(addr))

#define MMA_F16(d, a, b)                                                       \
    asm volatile("mma.sync.aligned.m16n8k16.row.col.f32.f16.f16.f32 "          \
                 "{%0,%1,%2,%3}, {%4,%5,%6,%7}, {%8,%9}, {%0,%1,%2,%3};"       \
                 : "+f"((d)[0]), "+f"((d)[1]), "+f"((d)[2]), "+f"((d)[3])      \
                 : "r"((a)[0]), "r"((a)[1]), "r"((a)[2]), "r"((a)[3]),         \
                   "r"((b)[0]), "r"((b)[1]))

#define CP_ASYNC16(sm, gm)                                                     \
    asm volatile("cp.async.cg.shared.global [%0], [%1], 16;"                   \
                 :: "r"(sm), "l"(gm) : "memory")
#define CP_COMMIT() asm volatile("cp.async.commit_group;" ::: "memory")
#define CP_WAIT0()  asm volatile("cp.async.wait_group 0;" ::: "memory")

// ---------------------------------------------------------------------------
// Prep: W [192][N] fp32 -> [N][192] fp16 hi(/lo)
// ---------------------------------------------------------------------------
__global__ void splitW_kernel(const float* __restrict__ W,
                              __half* __restrict__ h, __half* __restrict__ l,
                              int N) {
    int idx = blockIdx.x * blockDim.x + threadIdx.x;
    if (idx >= N * 192) return;
    int n = idx / 192, k = idx - n * 192;
    float v = W[(size_t)k * N + n];
    __half hh = __float2half_rn(v);
    h[idx] = hh;
    if (l) l[idx] = __float2half_rn(v - __half2float(hh));
}

// ---------------------------------------------------------------------------
// K0: bias gather (fp16 out), 16x split, float2-vectorized table reads
// ---------------------------------------------------------------------------
__global__ void bias_gather_kernel(const float* __restrict__ table,
                                   const int* __restrict__ pidx) {
    const int nw = blockIdx.x >> 4;
    const int part = blockIdx.x & 15;
    const size_t dbase = (size_t)nw * HEADS * (LTOK * LTOK);
    for (int i = part * 1296 + threadIdx.x; i < (part + 1) * 1296; i += 256) {
        const int pi = pidx[i];
        const float2* src = reinterpret_cast<const float2*>(
            table + (size_t)pi * (NW * HEADS) + nw * HEADS);
        float2 a = src[0], b = src[1], c = src[2];
        g_bias[dbase + 0 * (LTOK * LTOK) + i] = __float2half_rn(a.x);
        g_bias[dbase + 1 * (LTOK * LTOK) + i] = __float2half_rn(a.y);
        g_bias[dbase + 2 * (LTOK * LTOK) + i] = __float2half_rn(b.x);
        g_bias[dbase + 3 * (LTOK * LTOK) + i] = __float2half_rn(b.y);
        g_bias[dbase + 4 * (LTOK * LTOK) + i] = __float2half_rn(c.x);
        g_bias[dbase + 5 * (LTOK * LTOK) + i] = __float2half_rn(c.y);
    }
}

// ---------------------------------------------------------------------------
// fp16 GEMM, cp.async pipelined. npass=1: C=A@Bh. npass=2: C=A@(Bh+Bl).
// mode 0: A fp32 -> scatter Qh(scaled)/Kh/Vh+Vl head-major; mode 1 -> out.
// ---------------------------------------------------------------------------
#define ASTR 200
#define GEMM_SMEM ((128 * ASTR + 2 * 64 * ASTR) * 2)  // 102400 B

__global__ __launch_bounds__(256, 2) void mma_gemm_kernel(
    const void* __restrict__ Ain, const __half* __restrict__ Bh,
    const __half* __restrict__ Bl, const float* __restrict__ bias,
    int ntiles, int mode, int npass, float* __restrict__ out) {
    extern __shared__ __align__(16) __half sb[];
    __half* sA  = sb;                      // [128][ASTR]
    __half* sBh = sb + 128 * ASTR;         // [64][ASTR]
    __half* sBl = sBh + 64 * ASTR;

    const int tid = threadIdx.x;
    const int warp = tid >> 5, lane = tid & 31;
    const int warpm = warp >> 1, warpn = warp & 1;
    const int m_blk = blockIdx.x * 128;

    // ---- issue B tile 0 loads (async) ----
    {
#pragma unroll
        for (int it = 0; it < 6; it++) {
            int i = tid + it * 256;
            int r = i / 24, c = (i % 24) * 8;
            CP_ASYNC16(smem_u32(&sBh[r * ASTR + c]),
                       (const void*)&Bh[(size_t)r * 192 + c]);
            if (npass == 2)
                CP_ASYNC16(smem_u32(&sBl[r * ASTR + c]),
                           (const void*)&Bl[(size_t)r * 192 + c]);
        }
        CP_COMMIT();
    }

    // ---- stage A ----
    if (mode == 1) {
        const __half* A = (const __half*)Ain;
        for (int i = tid; i < 128 * 24; i += 256) {
            int r = i / 24, c = (i % 24) * 8;
            *reinterpret_cast<uint4*>(&sA[r * ASTR + c]) =
                *reinterpret_cast<const uint4*>(&A[(size_t)(m_blk + r) * 192 + c]);
        }
    } else {
        const float* A = (const float*)Ain;
        for (int i = tid; i < 128 * 48; i += 256) {
            int r = i / 48, c4 = (i % 48) * 4;
            float4 v = *reinterpret_cast<const float4*>(&A[(size_t)(m_blk + r) * 192 + c4]);
            *reinterpret_cast<__half2*>(&sA[r * ASTR + c4]) = __floats2half2_rn(v.x, v.y);
            *reinterpret_cast<__half2*>(&sA[r * ASTR + c4 + 2]) = __floats2half2_rn(v.z, v.w);
        }
    }
    CP_WAIT0();
    __syncthreads();

    const int lr = lane & 7, sel = lane >> 3;
    const int a_row_off = lr + (sel & 1) * 8;
    const int a_col_off = (sel >> 1) * 8;
    const int b_row_off = lr + (sel >> 1) * 8;
    const int b_col_off = (sel & 1) * 8;
    const int qrow = lane >> 2;
    const int qcol = (lane & 3) * 2;

    int rbi[4], rli[4];
#pragma unroll
    for (int i = 0; i < 4; i++) {
        int r = m_blk + warpm * 32 + (i >> 1) * 16 + (i & 1) * 8 + qrow;
        rbi[i] = r / LTOK;
        rli[i] = r - rbi[i] * LTOK;
    }

    for (int nt = 0; nt < ntiles; nt++) {
        float acc[2][4][4];
#pragma unroll
        for (int mt = 0; mt < 2; mt++)
#pragma unroll
            for (int t4 = 0; t4 < 4; t4++)
#pragma unroll
                for (int j = 0; j < 4; j++) acc[mt][t4][j] = 0.f;

#pragma unroll 4
        for (int ks = 0; ks < 12; ks++) {
            const int k0 = ks * 16;
            uint32_t a[2][4], bh[4][2];
#pragma unroll
            for (int mt = 0; mt < 2; mt++) {
                int row = warpm * 32 + mt * 16 + a_row_off;
                LDSM_X4(a[mt][0], a[mt][1], a[mt][2], a[mt][3],
                        smem_u32(&sA[row * ASTR + k0 + a_col_off]));
            }
#pragma unroll
            for (int pr = 0; pr < 2; pr++) {
                int row = warpn * 32 + pr * 16 + b_row_off;
                LDSM_X4(bh[2 * pr][0], bh[2 * pr][1], bh[2 * pr + 1][0],
                        bh[2 * pr + 1][1],
                        smem_u32(&sBh[row * ASTR + k0 + b_col_off]));
            }
#pragma unroll
            for (int mt = 0; mt < 2; mt++)
#pragma unroll
                for (int t4 = 0; t4 < 4; t4++)
                    MMA_F16(acc[mt][t4], a[mt], bh[t4]);
            if (npass == 2) {
                uint32_t bl[4][2];
#pragma unroll
                for (int pr = 0; pr < 2; pr++) {
                    int row = warpn * 32 + pr * 16 + b_row_off;
                    LDSM_X4(bl[2 * pr][0], bl[2 * pr][1], bl[2 * pr + 1][0],
                            bl[2 * pr + 1][1],
                            smem_u32(&sBl[row * ASTR + k0 + b_col_off]));
                }
#pragma unroll
                for (int mt = 0; mt < 2; mt++)
#pragma unroll
                    for (int t4 = 0; t4 < 4; t4++)
                        MMA_F16(acc[mt][t4], a[mt], bl[t4]);
            }
        }
        __syncthreads();  // all warps done reading sB

        // ---- issue next B tile loads (hidden under epilogue) ----
        if (nt + 1 < ntiles) {
            const size_t nb = (size_t)(nt + 1) * 64;
#pragma unroll
            for (int it = 0; it < 6; it++) {
                int i = tid + it * 256;
                int r = i / 24, c = (i % 24) * 8;
                CP_ASYNC16(smem_u32(&sBh[r * ASTR + c]),
                           (const void*)&Bh[(nb + r) * 192 + c]);
                if (npass == 2)
                    CP_ASYNC16(smem_u32(&sBl[r * ASTR + c]),
                               (const void*)&Bl[(nb + r) * 192 + c]);
            }
            CP_COMMIT();
        }

        // ---- epilogue(nt) ----
        if (mode == 1) {
#pragma unroll
            for (int t4 = 0; t4 < 4; t4++) {
                const int col = nt * 64 + warpn * 32 + t4 * 8 + qcol;
                const float b0 = bias[col], b1 = bias[col + 1];
#pragma unroll
                for (int mt = 0; mt < 2; mt++) {
                    const int r0 = m_blk + warpm * 32 + mt * 16 + qrow;
                    *reinterpret_cast<float2*>(&out[(size_t)r0 * CDIM + col]) =
                        make_float2(acc[mt][t4][0] + b0, acc[mt][t4][1] + b1);
                    *reinterpret_cast<float2*>(&out[(size_t)(r0 + 8) * CDIM + col]) =
                        make_float2(acc[mt][t4][2] + b0, acc[mt][t4][3] + b1);
                }
            }
        } else {
#pragma unroll
            for (int t4 = 0; t4 < 4; t4++) {
                const int col = nt * 64 + warpn * 32 + t4 * 8 + qcol;
                const int t = (col >= 2 * CDIM) ? 2 : ((col >= CDIM) ? 1 : 0);
                const int rem = col - t * CDIM;
                const int hh = rem >> 5, dd = rem & 31;
                const float b0 = bias[col], b1 = bias[col + 1];
#pragma unroll
                for (int mt = 0; mt < 2; mt++) {
                    const int i0 = mt * 2, i1 = mt * 2 + 1;
                    const size_t o0 =
                        ((size_t)(rbi[i0] * HEADS + hh) * LTOK + rli[i0]) * HD + dd;
                    const size_t o1 =
                        ((size_t)(rbi[i1] * HEADS + hh) * LTOK + rli[i1]) * HD + dd;
                    float v00 = acc[mt][t4][0] + b0, v01 = acc[mt][t4][1] + b1;
                    float v10 = acc[mt][t4][2] + b0, v11 = acc[mt][t4][3] + b1;
                    if (t == 0) {
                        *reinterpret_cast<__half2*>(g_Qh + o0) =
                            __floats2half2_rn(v00 * QK_SCALE, v01 * QK_SCALE);
                        *reinterpret_cast<__half2*>(g_Qh + o1) =
                            __floats2half2_rn(v10 * QK_SCALE, v11 * QK_SCALE);
                    } else if (t == 1) {
                        *reinterpret_cast<__half2*>(g_Kh + o0) =
                            __floats2half2_rn(v00, v01);
                        *reinterpret_cast<__half2*>(g_Kh + o1) =
                            __floats2half2_rn(v10, v11);
                    } else {
                        __half ha, la, hb, lb;
                        hsplit(v00, ha, la); hsplit(v01, hb, lb);
                        *reinterpret_cast<__half2*>(g_Vh + o0) = __halves2half2(ha, hb);
                        *reinterpret_cast<__half2*>(g_Vl + o0) = __halves2half2(la, lb);
                        hsplit(v10, ha, la); hsplit(v11, hb, lb);
                        *reinterpret_cast<__half2*>(g_Vh + o1) = __halves2half2(ha, hb);
                        *reinterpret_cast<__half2*>(g_Vl + o1) = __halves2half2(la, lb);
                    }
                }
            }
        }
        if (nt + 1 < ntiles) CP_WAIT0();
        __syncthreads();
    }
}

// ---------------------------------------------------------------------------
// K2: online-softmax mma attention. S = Qh@Kh (1-pass), PV = P@(Vh+Vl).
// 288 thr, 2 CTA/SM.
// ---------------------------------------------------------------------------
#define QSTR 40
#define VTSTR 152
#define ATTN_SMEM (2 * 144 * QSTR * 2 + 2 * 32 * VTSTR * 2)   // 42496 B

__global__ __launch_bounds__(288, 2) void attn_mma_kernel(const float* __restrict__ mask) {
    extern __shared__ __align__(16) char sraw[];
    __half* sQh = reinterpret_cast<__half*>(sraw);
    __half* sKh = sQh + 144 * QSTR;
    __half* sVh = sKh + 144 * QSTR;          // [32][VTSTR] transposed
    __half* sVl = sVh + 32 * VTSTR;

    const int bh = blockIdx.x;
    const int b = bh / HEADS, h = bh % HEADS;
    const int nw = b / WWINS;
    const int tid = threadIdx.x;
    const int warp = tid >> 5, lane = tid & 31;
    const size_t base = (size_t)bh * (LTOK * HD);

    for (int c = tid; c < 576; c += 288) {
        int l = c >> 2, dp = (c & 3) * 8;
        *reinterpret_cast<uint4*>(&sQh[l * QSTR + dp]) =
            *reinterpret_cast<const uint4*>(&g_Qh[base + l * 32 + dp]);
        *reinterpret_cast<uint4*>(&sKh[l * QSTR + dp]) =
            *reinterpret_cast<const uint4*>(&g_Kh[base + l * 32 + dp]);
    }
    for (int i = tid; i < 2304; i += 288) {
        int l = i >> 4, d2 = (i & 15) * 2;
        __half2 vh = *reinterpret_cast<const __half2*>(&g_Vh[base + l * 32 + d2]);
        __half2 vl = *reinterpret_cast<const __half2*>(&g_Vl[base + l * 32 + d2]);
        sVh[d2 * VTSTR + l] = __low2half(vh);
        sVh[(d2 + 1) * VTSTR + l] = __high2half(vh);
        sVl[d2 * VTSTR + l] = __low2half(vl);
        sVl[(d2 + 1) * VTSTR + l] = __high2half(vl);
    }
    __syncthreads();

    const int lr = lane & 7, sel = lane >> 3;
    const int arow = lr + (sel & 1) * 8, acol = (sel >> 1) * 8;
    const int brow = lr + (sel >> 1) * 8, bcol = (sel & 1) * 8;
    const int g = lane >> 2, tg = lane & 3;

    uint32_t qh[2][4];
#pragma unroll
    for (int ks = 0; ks < 2; ks++) {
        LDSM_X4(qh[ks][0], qh[ks][1], qh[ks][2], qh[ks][3],
                smem_u32(&sQh[(warp * 16 + arow) * QSTR + ks * 16 + acol]));
    }

    const __half* biasrow = g_bias + (size_t)(nw * HEADS + h) * (LTOK * LTOK);
    const float* maskrow = mask + (size_t)b * (LTOK * LTOK);
    const int r0 = warp * 16 + g;
    const int r1 = r0 + 8;

    float m0 = -1e30f, m1 = -1e30f, s0 = 0.f, s1 = 0.f;
    float o[4][4];
#pragma unroll
    for (int nb = 0; nb < 4; nb++)
#pragma unroll
        for (int j = 0; j < 4; j++) o[nb][j] = 0.f;

#pragma unroll 1
    for (int ch = 0; ch < 3; ch++) {
        float acc[6][4];
#pragma unroll
        for (int nb = 0; nb < 6; nb++)
#pragma unroll
            for (int j = 0; j < 4; j++) acc[nb][j] = 0.f;

#pragma unroll
        for (int j = 0; j < 3; j++) {
            const int nt = 3 * ch + j;
#pragma unroll
            for (int ks = 0; ks < 2; ks++) {
                uint32_t kh[4];
                LDSM_X4(kh[0], kh[1], kh[2], kh[3],
                        smem_u32(&sKh[(nt * 16 + brow) * QSTR + ks * 16 + bcol]));
                MMA_F16(acc[2 * j],     qh[ks], kh + 0);
                MMA_F16(acc[2 * j + 1], qh[ks], kh + 2);
            }
        }

#pragma unroll
        for (int nb = 0; nb < 6; nb++) {
            const int cc = 48 * ch + nb * 8 + tg * 2;
            float2 b0 = __half22float2(
                *reinterpret_cast<const __half2*>(&biasrow[r0 * LTOK + cc]));
            float2 m0v = *reinterpret_cast<const float2*>(&maskrow[r0 * LTOK + cc]);
            float2 b1 = __half22float2(
                *reinterpret_cast<const __half2*>(&biasrow[r1 * LTOK + cc]));
            float2 m1v = *reinterpret_cast<const float2*>(&maskrow[r1 * LTOK + cc]);
            acc[nb][0] += b0.x + m0v.x;
            acc[nb][1] += b0.y + m0v.y;
            acc[nb][2] += b1.x + m1v.x;
            acc[nb][3] += b1.y + m1v.y;
        }

        float cm0 = -1e30f, cm1 = -1e30f;
#pragma unroll
        for (int nb = 0; nb < 6; nb++) {
            cm0 = fmaxf(cm0, fmaxf(acc[nb][0], acc[nb][1]));
            cm1 = fmaxf(cm1, fmaxf(acc[nb][2], acc[nb][3]));
        }
        cm0 = fmaxf(cm0, __shfl_xor_sync(0xffffffffu, cm0, 1));
        cm0 = fmaxf(cm0, __shfl_xor_sync(0xffffffffu, cm0, 2));
        cm1 = fmaxf(cm1, __shfl_xor_sync(0xffffffffu, cm1, 1));
        cm1 = fmaxf(cm1, __shfl_xor_sync(0xffffffffu, cm1, 2));
        const float nm0 = fmaxf(m0, cm0);
        const float nm1 = fmaxf(m1, cm1);
        const float sc0 = fexp(m0 - nm0);
        const float sc1 = fexp(m1 - nm1);
        m0 = nm0; m1 = nm1;
        s0 *= sc0; s1 *= sc1;
#pragma unroll
        for (int nb = 0; nb < 4; nb++) {
            o[nb][0] *= sc0; o[nb][1] *= sc0;
            o[nb][2] *= sc1; o[nb][3] *= sc1;
        }

#pragma unroll
        for (int nb = 0; nb < 6; nb++) {
            acc[nb][0] = fexp(acc[nb][0] - nm0);
            acc[nb][1] = fexp(acc[nb][1] - nm0);
            acc[nb][2] = fexp(acc[nb][2] - nm1);
            acc[nb][3] = fexp(acc[nb][3] - nm1);
            s0 += acc[nb][0] + acc[nb][1];
            s1 += acc[nb][2] + acc[nb][3];
        }

#pragma unroll
        for (int k = 0; k < 3; k++) {
            const int ksg = 3 * ch + k;
            uint32_t a[4];
            a[0] = pack_h2(acc[2 * k][0], acc[2 * k][1]);
            a[1] = pack_h2(acc[2 * k][2], acc[2 * k][3]);
            a[2] = pack_h2(acc[2 * k + 1][0], acc[2 * k + 1][1]);
            a[3] = pack_h2(acc[2 * k + 1][2], acc[2 * k + 1][3]);
#pragma unroll
            for (int ntv = 0; ntv < 2; ntv++) {
                uint32_t vh[4], vl[4];
                LDSM_X4(vh[0], vh[1], vh[2], vh[3],
                        smem_u32(&sVh[(ntv * 16 + brow) * VTSTR + ksg * 16 + bcol]));
                LDSM_X4(vl[0], vl[1], vl[2], vl[3],
                        smem_u32(&sVl[(ntv * 16 + brow) * VTSTR + ksg * 16 + bcol]));
                MMA_F16(o[2 * ntv],     a, vh + 0);
                MMA_F16(o[2 * ntv + 1], a, vh + 2);
                MMA_F16(o[2 * ntv],     a, vl + 0);
                MMA_F16(o[2 * ntv + 1], a, vl + 2);
            }
        }
    }

    s0 += __shfl_xor_sync(0xffffffffu, s0, 1);
    s0 += __shfl_xor_sync(0xffffffffu, s0, 2);
    s1 += __shfl_xor_sync(0xffffffffu, s1, 1);
    s1 += __shfl_xor_sync(0xffffffffu, s1, 2);
    const float inv0 = 1.f / s0, inv1 = 1.f / s1;

#pragma unroll
    for (int nb = 0; nb < 4; nb++) {
        const int d0 = nb * 8 + tg * 2;
        const size_t off0 = ((size_t)b * LTOK + r0) * CDIM + h * HD + d0;
        const size_t off1 = ((size_t)b * LTOK + r1) * CDIM + h * HD + d0;
        *reinterpret_cast<__half2*>(&g_ctx[off0]) =
            __floats2half2_rn(o[nb][0] * inv0, o[nb][1] * inv0);
        *reinterpret_cast<__half2*>(&g_ctx[off1]) =
            __floats2half2_rn(o[nb][2] * inv1, o[nb][3] * inv1);
    }
}

// ---------------------------------------------------------------------------
extern "C" void kernel_launch(void* const* d_in, const int* in_sizes, int n_in,
                              void* d_out, int out_size) {
    const float* x    = (const float*)d_in[0];
    const float* mask = (const float*)d_in[1];
    const float* W1   = (const float*)d_in[2];
    const float* b1   = (const float*)d_in[3];
    const float* W2   = (const float*)d_in[4];
    const float* b2   = (const float*)d_in[5];
    const float* btab = (const float*)d_in[6];
    const int*   pidx = (const int*)d_in[7];
    float* out = (float*)d_out;
    (void)in_sizes; (void)n_in; (void)out_size;

    cudaFuncSetAttribute(mma_gemm_kernel,
                         cudaFuncAttributeMaxDynamicSharedMemorySize, GEMM_SMEM);
    cudaFuncSetAttribute(attn_mma_kernel,
                         cudaFuncAttributeMaxDynamicSharedMemorySize, ATTN_SMEM);

    __half *w1h, *w2h, *w2l, *ctx;
    cudaGetSymbolAddress((void**)&w1h, g_W1h);
    cudaGetSymbolAddress((void**)&w2h, g_W2h);
    cudaGetSymbolAddress((void**)&w2l, g_W2l);
    cudaGetSymbolAddress((void**)&ctx, g_ctx);

    splitW_kernel<<<(576 * 192 + 255) / 256, 256>>>(W1, w1h, nullptr, 576);
    splitW_kernel<<<(192 * 192 + 255) / 256, 256>>>(W2, w2h, w2l, 192);
    bias_gather_kernel<<<NW * 16, 256>>>(btab, pidx);

    mma_gemm_kernel<<<MTOT / 128, 256, GEMM_SMEM>>>(x, w1h, nullptr, b1, 9, 0, 1, nullptr);
    attn_mma_kernel<<<NWIN * HEADS, 288, ATTN_SMEM>>>(mask);
    mma_gemm_kernel<<<MTOT / 128, 256, GEMM_SMEM>>>(ctx, w2h, w2l, b2, 3, 1, 2, out);
}

// round 13
// speedup vs baseline: 1.5754x; 1.0729x over previous
#include <cuda_runtime.h>
#include <cuda_bf16.h>
#include <cuda_fp16.h>
#include <cstdint>

// ---------------------------------------------------------------------------
// EarthAttention3D: B_=960, L=144, C=192, H=6, hd=32, NUM_WINDOWS=64, W_WINS=15
// Round 13: drop Vl (PV single-pass) — attn MMAs -33%; error budget holds
// (~5e-4 vs 1e-3). QKV 1-pass, out-proj 2-pass, online-softmax attention.
// ---------------------------------------------------------------------------

#define NWIN   960
#define LTOK   144
#define CDIM   192
#define HEADS  6
#define HD     32
#define NW     64
#define WWINS  15
#define MTOT   (NWIN * LTOK)          // 138240
#define QK_SCALE 0.17677669529663687f

// ------------------------- scratch (device globals) ------------------------
__device__ __half g_bias[NW * HEADS * LTOK * LTOK];
__device__ __half g_ctx[MTOT * CDIM];
__device__ __half g_Qh[NWIN * HEADS * LTOK * HD];
__device__ __half g_Kh[NWIN * HEADS * LTOK * HD];
__device__ __half g_Vh[NWIN * HEADS * LTOK * HD];
__device__ __half g_W1h[576 * 192];
__device__ __half g_W2h[192 * 192];
__device__ __half g_W2l[192 * 192];

// ------------------------------ helpers ------------------------------------
__device__ __forceinline__ uint32_t smem_u32(const void* p) {
    uint32_t a;
    asm("{ .reg .u64 t; cvta.to.shared.u64 t, %1; cvt.u32.u64 %0, t; }"
        : "=r"(a) : "l"(p));
    return a;
}
__device__ __forceinline__ uint32_t pack_h2(float a, float b) {
    __half2 t = __floats2half2_rn(a, b);
    return *reinterpret_cast<uint32_t*>(&t);
}
// exp(x) on the FMA pipe
__device__ __forceinline__ float fexp(float x) {
    float y = fmaxf(x * 1.4426950408889634f, -126.0f);
    float n = rintf(y);
    float f = y - n;
    float p = 0.0013333558f;
    p = fmaf(p, f, 0.009618129f);
    p = fmaf(p, f, 0.055504109f);
    p = fmaf(p, f, 0.24022651f);
    p = fmaf(p, f, 0.69314718f);
    p = fmaf(p, f, 1.0f);
    return __int_as_float(((int)n + 127) << 23) * p;
}

#define LDSM_X4(r0, r1, r2, r3, addr)                                          \
    asm volatile("ldmatrix.sync.aligned.m8n8.x4.shared.b16 {%0,%1,%2,%3}, [%4];" \
                 : "=r"(r0), "=r"(r1), "=r"(r2), "=r"(r3) : "r"(addr))

#define MMA_F16(d, a, b)                                                       \
    asm volatile("mma.sync.aligned.m16n8k16.row.col.f32.f16.f16.f32 "          \
                 "{%0,%1,%2,%3}, {%4,%5,%6,%7}, {%8,%9}, {%0,%1,%2,%3};"       \
                 : "+f"((d)[0]), "+f"((d)[1]), "+f"((d)[2]), "+f"((d)[3])      \
                 : "r"((a)[0]), "r"((a)[1]), "r"((a)[2]), "r"((a)[3]),         \
                   "r"((b)[0]), "r"((b)[1]))

#define CP_ASYNC16(sm, gm)                                                     \
    asm volatile("cp.async.cg.shared.global [%0], [%1], 16;"                   \
                 :: "r"(sm), "l"(gm) : "memory")
#define CP_COMMIT() asm volatile("cp.async.commit_group;" ::: "memory")
#define CP_WAIT0()  asm volatile("cp.async.wait_group 0;" ::: "memory")

// ---------------------------------------------------------------------------
// Prep: W [192][N] fp32 -> [N][192] fp16 hi(/lo)
// ---------------------------------------------------------------------------
__global__ void splitW_kernel(const float* __restrict__ W,
                              __half* __restrict__ h, __half* __restrict__ l,
                              int N) {
    int idx = blockIdx.x * blockDim.x + threadIdx.x;
    if (idx >= N * 192) return;
    int n = idx / 192, k = idx - n * 192;
    float v = W[(size_t)k * N + n];
    __half hh = __float2half_rn(v);
    h[idx] = hh;
    if (l) l[idx] = __float2half_rn(v - __half2float(hh));
}

// ---------------------------------------------------------------------------
// K0: bias gather (fp16 out), 16x split, float2-vectorized table reads
// ---------------------------------------------------------------------------
__global__ void bias_gather_kernel(const float* __restrict__ table,
                                   const int* __restrict__ pidx) {
    const int nw = blockIdx.x >> 4;
    const int part = blockIdx.x & 15;
    const size_t dbase = (size_t)nw * HEADS * (LTOK * LTOK);
    for (int i = part * 1296 + threadIdx.x; i < (part + 1) * 1296; i += 256) {
        const int pi = pidx[i];
        const float2* src = reinterpret_cast<const float2*>(
            table + (size_t)pi * (NW * HEADS) + nw * HEADS);
        float2 a = src[0], b = src[1], c = src[2];
        g_bias[dbase + 0 * (LTOK * LTOK) + i] = __float2half_rn(a.x);
        g_bias[dbase + 1 * (LTOK * LTOK) + i] = __float2half_rn(a.y);
        g_bias[dbase + 2 * (LTOK * LTOK) + i] = __float2half_rn(b.x);
        g_bias[dbase + 3 * (LTOK * LTOK) + i] = __float2half_rn(b.y);
        g_bias[dbase + 4 * (LTOK * LTOK) + i] = __float2half_rn(c.x);
        g_bias[dbase + 5 * (LTOK * LTOK) + i] = __float2half_rn(c.y);
    }
}

// ---------------------------------------------------------------------------
// fp16 GEMM, cp.async pipelined. npass=1: C=A@Bh. npass=2: C=A@(Bh+Bl).
// mode 0: A fp32 -> scatter Qh(scaled)/Kh/Vh head-major; mode 1 -> out.
// ---------------------------------------------------------------------------
#define ASTR 200
#define GEMM_SMEM ((128 * ASTR + 2 * 64 * ASTR) * 2)  // 102400 B

__global__ __launch_bounds__(256, 2) void mma_gemm_kernel(
    const void* __restrict__ Ain, const __half* __restrict__ Bh,
    const __half* __restrict__ Bl, const float* __restrict__ bias,
    int ntiles, int mode, int npass, float* __restrict__ out) {
    extern __shared__ __align__(16) __half sb[];
    __half* sA  = sb;                      // [128][ASTR]
    __half* sBh = sb + 128 * ASTR;         // [64][ASTR]
    __half* sBl = sBh + 64 * ASTR;

    const int tid = threadIdx.x;
    const int warp = tid >> 5, lane = tid & 31;
    const int warpm = warp >> 1, warpn = warp & 1;
    const int m_blk = blockIdx.x * 128;

    // ---- issue B tile 0 loads (async) ----
    {
#pragma unroll
        for (int it = 0; it < 6; it++) {
            int i = tid + it * 256;
            int r = i / 24, c = (i % 24) * 8;
            CP_ASYNC16(smem_u32(&sBh[r * ASTR + c]),
                       (const void*)&Bh[(size_t)r * 192 + c]);
            if (npass == 2)
                CP_ASYNC16(smem_u32(&sBl[r * ASTR + c]),
                           (const void*)&Bl[(size_t)r * 192 + c]);
        }
        CP_COMMIT();
    }

    // ---- stage A ----
    if (mode == 1) {
        const __half* A = (const __half*)Ain;
        for (int i = tid; i < 128 * 24; i += 256) {
            int r = i / 24, c = (i % 24) * 8;
            *reinterpret_cast<uint4*>(&sA[r * ASTR + c]) =
                *reinterpret_cast<const uint4*>(&A[(size_t)(m_blk + r) * 192 + c]);
        }
    } else {
        const float* A = (const float*)Ain;
        for (int i = tid; i < 128 * 48; i += 256) {
            int r = i / 48, c4 = (i % 48) * 4;
            float4 v = *reinterpret_cast<const float4*>(&A[(size_t)(m_blk + r) * 192 + c4]);
            *reinterpret_cast<__half2*>(&sA[r * ASTR + c4]) = __floats2half2_rn(v.x, v.y);
            *reinterpret_cast<__half2*>(&sA[r * ASTR + c4 + 2]) = __floats2half2_rn(v.z, v.w);
        }
    }
    CP_WAIT0();
    __syncthreads();

    const int lr = lane & 7, sel = lane >> 3;
    const int a_row_off = lr + (sel & 1) * 8;
    const int a_col_off = (sel >> 1) * 8;
    const int b_row_off = lr + (sel >> 1) * 8;
    const int b_col_off = (sel & 1) * 8;
    const int qrow = lane >> 2;
    const int qcol = (lane & 3) * 2;

    int rbi[4], rli[4];
#pragma unroll
    for (int i = 0; i < 4; i++) {
        int r = m_blk + warpm * 32 + (i >> 1) * 16 + (i & 1) * 8 + qrow;
        rbi[i] = r / LTOK;
        rli[i] = r - rbi[i] * LTOK;
    }

    for (int nt = 0; nt < ntiles; nt++) {
        float acc[2][4][4];
#pragma unroll
        for (int mt = 0; mt < 2; mt++)
#pragma unroll
            for (int t4 = 0; t4 < 4; t4++)
#pragma unroll
                for (int j = 0; j < 4; j++) acc[mt][t4][j] = 0.f;

#pragma unroll 4
        for (int ks = 0; ks < 12; ks++) {
            const int k0 = ks * 16;
            uint32_t a[2][4], bh[4][2];
#pragma unroll
            for (int mt = 0; mt < 2; mt++) {
                int row = warpm * 32 + mt * 16 + a_row_off;
                LDSM_X4(a[mt][0], a[mt][1], a[mt][2], a[mt][3],
                        smem_u32(&sA[row * ASTR + k0 + a_col_off]));
            }
#pragma unroll
            for (int pr = 0; pr < 2; pr++) {
                int row = warpn * 32 + pr * 16 + b_row_off;
                LDSM_X4(bh[2 * pr][0], bh[2 * pr][1], bh[2 * pr + 1][0],
                        bh[2 * pr + 1][1],
                        smem_u32(&sBh[row * ASTR + k0 + b_col_off]));
            }
#pragma unroll
            for (int mt = 0; mt < 2; mt++)
#pragma unroll
                for (int t4 = 0; t4 < 4; t4++)
                    MMA_F16(acc[mt][t4], a[mt], bh[t4]);
            if (npass == 2) {
                uint32_t bl[4][2];
#pragma unroll
                for (int pr = 0; pr < 2; pr++) {
                    int row = warpn * 32 + pr * 16 + b_row_off;
                    LDSM_X4(bl[2 * pr][0], bl[2 * pr][1], bl[2 * pr + 1][0],
                            bl[2 * pr + 1][1],
                            smem_u32(&sBl[row * ASTR + k0 + b_col_off]));
                }
#pragma unroll
                for (int mt = 0; mt < 2; mt++)
#pragma unroll
                    for (int t4 = 0; t4 < 4; t4++)
                        MMA_F16(acc[mt][t4], a[mt], bl[t4]);
            }
        }
        __syncthreads();  // all warps done reading sB

        // ---- issue next B tile loads (hidden under epilogue) ----
        if (nt + 1 < ntiles) {
            const size_t nb = (size_t)(nt + 1) * 64;
#pragma unroll
            for (int it = 0; it < 6; it++) {
                int i = tid + it * 256;
                int r = i / 24, c = (i % 24) * 8;
                CP_ASYNC16(smem_u32(&sBh[r * ASTR + c]),
                           (const void*)&Bh[(nb + r) * 192 + c]);
                if (npass == 2)
                    CP_ASYNC16(smem_u32(&sBl[r * ASTR + c]),
                               (const void*)&Bl[(nb + r) * 192 + c]);
            }
            CP_COMMIT();
        }

        // ---- epilogue(nt) ----
        if (mode == 1) {
#pragma unroll
            for (int t4 = 0; t4 < 4; t4++) {
                const int col = nt * 64 + warpn * 32 + t4 * 8 + qcol;
                const float b0 = bias[col], b1 = bias[col + 1];
#pragma unroll
                for (int mt = 0; mt < 2; mt++) {
                    const int r0 = m_blk + warpm * 32 + mt * 16 + qrow;
                    *reinterpret_cast<float2*>(&out[(size_t)r0 * CDIM + col]) =
                        make_float2(acc[mt][t4][0] + b0, acc[mt][t4][1] + b1);
                    *reinterpret_cast<float2*>(&out[(size_t)(r0 + 8) * CDIM + col]) =
                        make_float2(acc[mt][t4][2] + b0, acc[mt][t4][3] + b1);
                }
            }
        } else {
#pragma unroll
            for (int t4 = 0; t4 < 4; t4++) {
                const int col = nt * 64 + warpn * 32 + t4 * 8 + qcol;
                const int t = (col >= 2 * CDIM) ? 2 : ((col >= CDIM) ? 1 : 0);
                const int rem = col - t * CDIM;
                const int hh = rem >> 5, dd = rem & 31;
                const float b0 = bias[col], b1 = bias[col + 1];
                __half* dst = (t == 0) ? g_Qh : ((t == 1) ? g_Kh : g_Vh);
                const float sc = (t == 0) ? QK_SCALE : 1.0f;
#pragma unroll
                for (int mt = 0; mt < 2; mt++) {
                    const int i0 = mt * 2, i1 = mt * 2 + 1;
                    const size_t o0 =
                        ((size_t)(rbi[i0] * HEADS + hh) * LTOK + rli[i0]) * HD + dd;
                    const size_t o1 =
                        ((size_t)(rbi[i1] * HEADS + hh) * LTOK + rli[i1]) * HD + dd;
                    *reinterpret_cast<__half2*>(dst + o0) = __floats2half2_rn(
                        (acc[mt][t4][0] + b0) * sc, (acc[mt][t4][1] + b1) * sc);
                    *reinterpret_cast<__half2*>(dst + o1) = __floats2half2_rn(
                        (acc[mt][t4][2] + b0) * sc, (acc[mt][t4][3] + b1) * sc);
                }
            }
        }
        if (nt + 1 < ntiles) CP_WAIT0();
        __syncthreads();
    }
}

// ---------------------------------------------------------------------------
// K2: online-softmax mma attention. S = Qh@Kh, PV = P@Vh (both 1-pass).
// 288 thr, 2 CTA/SM, 32.8 KB SMEM.
// ---------------------------------------------------------------------------
#define QSTR 40
#define VTSTR 152
#define ATTN_SMEM (2 * 144 * QSTR * 2 + 32 * VTSTR * 2)   // 32768 B

__global__ __launch_bounds__(288, 2) void attn_mma_kernel(const float* __restrict__ mask) {
    extern __shared__ __align__(16) char sraw[];
    __half* sQh = reinterpret_cast<__half*>(sraw);
    __half* sKh = sQh + 144 * QSTR;
    __half* sVh = sKh + 144 * QSTR;          // [32][VTSTR] transposed

    const int bh = blockIdx.x;
    const int b = bh / HEADS, h = bh % HEADS;
    const int nw = b / WWINS;
    const int tid = threadIdx.x;
    const int warp = tid >> 5, lane = tid & 31;
    const size_t base = (size_t)bh * (LTOK * HD);

    for (int c = tid; c < 576; c += 288) {
        int l = c >> 2, dp = (c & 3) * 8;
        *reinterpret_cast<uint4*>(&sQh[l * QSTR + dp]) =
            *reinterpret_cast<const uint4*>(&g_Qh[base + l * 32 + dp]);
        *reinterpret_cast<uint4*>(&sKh[l * QSTR + dp]) =
            *reinterpret_cast<const uint4*>(&g_Kh[base + l * 32 + dp]);
    }
    for (int i = tid; i < 2304; i += 288) {
        int l = i >> 4, d2 = (i & 15) * 2;
        __half2 vh = *reinterpret_cast<const __half2*>(&g_Vh[base + l * 32 + d2]);
        sVh[d2 * VTSTR + l] = __low2half(vh);
        sVh[(d2 + 1) * VTSTR + l] = __high2half(vh);
    }
    __syncthreads();

    const int lr = lane & 7, sel = lane >> 3;
    const int arow = lr + (sel & 1) * 8, acol = (sel >> 1) * 8;
    const int brow = lr + (sel >> 1) * 8, bcol = (sel & 1) * 8;
    const int g = lane >> 2, tg = lane & 3;

    uint32_t qh[2][4];
#pragma unroll
    for (int ks = 0; ks < 2; ks++) {
        LDSM_X4(qh[ks][0], qh[ks][1], qh[ks][2], qh[ks][3],
                smem_u32(&sQh[(warp * 16 + arow) * QSTR + ks * 16 + acol]));
    }

    const __half* biasrow = g_bias + (size_t)(nw * HEADS + h) * (LTOK * LTOK);
    const float* maskrow = mask + (size_t)b * (LTOK * LTOK);
    const int r0 = warp * 16 + g;
    const int r1 = r0 + 8;

    float m0 = -1e30f, m1 = -1e30f, s0 = 0.f, s1 = 0.f;
    float o[4][4];
#pragma unroll
    for (int nb = 0; nb < 4; nb++)
#pragma unroll
        for (int j = 0; j < 4; j++) o[nb][j] = 0.f;

#pragma unroll 1
    for (int ch = 0; ch < 3; ch++) {
        float acc[6][4];
#pragma unroll
        for (int nb = 0; nb < 6; nb++)
#pragma unroll
            for (int j = 0; j < 4; j++) acc[nb][j] = 0.f;

#pragma unroll
        for (int j = 0; j < 3; j++) {
            const int nt = 3 * ch + j;
#pragma unroll
            for (int ks = 0; ks < 2; ks++) {
                uint32_t kh[4];
                LDSM_X4(kh[0], kh[1], kh[2], kh[3],
                        smem_u32(&sKh[(nt * 16 + brow) * QSTR + ks * 16 + bcol]));
                MMA_F16(acc[2 * j],     qh[ks], kh + 0);
                MMA_F16(acc[2 * j + 1], qh[ks], kh + 2);
            }
        }

#pragma unroll
        for (int nb = 0; nb < 6; nb++) {
            const int cc = 48 * ch + nb * 8 + tg * 2;
            float2 b0 = __half22float2(
                *reinterpret_cast<const __half2*>(&biasrow[r0 * LTOK + cc]));
            float2 m0v = *reinterpret_cast<const float2*>(&maskrow[r0 * LTOK + cc]);
            float2 b1 = __half22float2(
                *reinterpret_cast<const __half2*>(&biasrow[r1 * LTOK + cc]));
            float2 m1v = *reinterpret_cast<const float2*>(&maskrow[r1 * LTOK + cc]);
            acc[nb][0] += b0.x + m0v.x;
            acc[nb][1] += b0.y + m0v.y;
            acc[nb][2] += b1.x + m1v.x;
            acc[nb][3] += b1.y + m1v.y;
        }

        float cm0 = -1e30f, cm1 = -1e30f;
#pragma unroll
        for (int nb = 0; nb < 6; nb++) {
            cm0 = fmaxf(cm0, fmaxf(acc[nb][0], acc[nb][1]));
            cm1 = fmaxf(cm1, fmaxf(acc[nb][2], acc[nb][3]));
        }
        cm0 = fmaxf(cm0, __shfl_xor_sync(0xffffffffu, cm0, 1));
        cm0 = fmaxf(cm0, __shfl_xor_sync(0xffffffffu, cm0, 2));
        cm1 = fmaxf(cm1, __shfl_xor_sync(0xffffffffu, cm1, 1));
        cm1 = fmaxf(cm1, __shfl_xor_sync(0xffffffffu, cm1, 2));
        const float nm0 = fmaxf(m0, cm0);
        const float nm1 = fmaxf(m1, cm1);
        const float sc0 = fexp(m0 - nm0);
        const float sc1 = fexp(m1 - nm1);
        m0 = nm0; m1 = nm1;
        s0 *= sc0; s1 *= sc1;
#pragma unroll
        for (int nb = 0; nb < 4; nb++) {
            o[nb][0] *= sc0; o[nb][1] *= sc0;
            o[nb][2] *= sc1; o[nb][3] *= sc1;
        }

#pragma unroll
        for (int nb = 0; nb < 6; nb++) {
            acc[nb][0] = fexp(acc[nb][0] - nm0);
            acc[nb][1] = fexp(acc[nb][1] - nm0);
            acc[nb][2] = fexp(acc[nb][2] - nm1);
            acc[nb][3] = fexp(acc[nb][3] - nm1);
            s0 += acc[nb][0] + acc[nb][1];
            s1 += acc[nb][2] + acc[nb][3];
        }

#pragma unroll
        for (int k = 0; k < 3; k++) {
            const int ksg = 3 * ch + k;
            uint32_t a[4];
            a[0] = pack_h2(acc[2 * k][0], acc[2 * k][1]);
            a[1] = pack_h2(acc[2 * k][2], acc[2 * k][3]);
            a[2] = pack_h2(acc[2 * k + 1][0], acc[2 * k + 1][1]);
            a[3] = pack_h2(acc[2 * k + 1][2], acc[2 * k + 1][3]);
#pragma unroll
            for (int ntv = 0; ntv < 2; ntv++) {
                uint32_t vh[4];
                LDSM_X4(vh[0], vh[1], vh[2], vh[3],
                        smem_u32(&sVh[(ntv * 16 + brow) * VTSTR + ksg * 16 + bcol]));
                MMA_F16(o[2 * ntv],     a, vh + 0);
                MMA_F16(o[2 * ntv + 1], a, vh + 2);
            }
        }
    }

    s0 += __shfl_xor_sync(0xffffffffu, s0, 1);
    s0 += __shfl_xor_sync(0xffffffffu, s0, 2);
    s1 += __shfl_xor_sync(0xffffffffu, s1, 1);
    s1 += __shfl_xor_sync(0xffffffffu, s1, 2);
    const float inv0 = 1.f / s0, inv1 = 1.f / s1;

#pragma unroll
    for (int nb = 0; nb < 4; nb++) {
        const int d0 = nb * 8 + tg * 2;
        const size_t off0 = ((size_t)b * LTOK + r0) * CDIM + h * HD + d0;
        const size_t off1 = ((size_t)b * LTOK + r1) * CDIM + h * HD + d0;
        *reinterpret_cast<__half2*>(&g_ctx[off0]) =
            __floats2half2_rn(o[nb][0] * inv0, o[nb][1] * inv0);
        *reinterpret_cast<__half2*>(&g_ctx[off1]) =
            __floats2half2_rn(o[nb][2] * inv1, o[nb][3] * inv1);
    }
}

// ---------------------------------------------------------------------------
extern "C" void kernel_launch(void* const* d_in, const int* in_sizes, int n_in,
                              void* d_out, int out_size) {
    const float* x    = (const float*)d_in[0];
    const float* mask = (const float*)d_in[1];
    const float* W1   = (const float*)d_in[2];
    const float* b1   = (const float*)d_in[3];
    const float* W2   = (const float*)d_in[4];
    const float* b2   = (const float*)d_in[5];
    const float* btab = (const float*)d_in[6];
    const int*   pidx = (const int*)d_in[7];
    float* out = (float*)d_out;
    (void)in_sizes; (void)n_in; (void)out_size;

    cudaFuncSetAttribute(mma_gemm_kernel,
                         cudaFuncAttributeMaxDynamicSharedMemorySize, GEMM_SMEM);
    cudaFuncSetAttribute(attn_mma_kernel,
                         cudaFuncAttributeMaxDynamicSharedMemorySize, ATTN_SMEM);

    __half *w1h, *w2h, *w2l, *ctx;
    cudaGetSymbolAddress((void**)&w1h, g_W1h);
    cudaGetSymbolAddress((void**)&w2h, g_W2h);
    cudaGetSymbolAddress((void**)&w2l, g_W2l);
    cudaGetSymbolAddress((void**)&ctx, g_ctx);

    splitW_kernel<<<(576 * 192 + 255) / 256, 256>>>(W1, w1h, nullptr, 576);
    splitW_kernel<<<(192 * 192 + 255) / 256, 256>>>(W2, w2h, w2l, 192);
    bias_gather_kernel<<<NW * 16, 256>>>(btab, pidx);

    mma_gemm_kernel<<<MTOT / 128, 256, GEMM_SMEM>>>(x, w1h, nullptr, b1, 9, 0, 1, nullptr);
    attn_mma_kernel<<<NWIN * HEADS, 288, ATTN_SMEM>>>(mask);
    mma_gemm_kernel<<<MTOT / 128, 256, GEMM_SMEM>>>(ctx, w2h, w2l, b2, 3, 1, 2, out);
}

// round 15
// speedup vs baseline: 1.7098x; 1.0853x over previous
#include <cuda_runtime.h>
#include <cuda_bf16.h>
#include <cuda_fp16.h>
#include <cstdint>

// ---------------------------------------------------------------------------
// EarthAttention3D: B_=960, L=144, C=192, H=6, hd=32, NUM_WINDOWS=64, W_WINS=15
// Round 14: out-proj single-pass (error budget holds ~5.1e-4), one-element-
// per-thread bias gather. QKV 1-pass, online-softmax attention (unchanged).
// ---------------------------------------------------------------------------

#define NWIN   960
#define LTOK   144
#define CDIM   192
#define HEADS  6
#define HD     32
#define NW     64
#define WWINS  15
#define MTOT   (NWIN * LTOK)          // 138240
#define QK_SCALE 0.17677669529663687f

// ------------------------- scratch (device globals) ------------------------
__device__ __half g_bias[NW * HEADS * LTOK * LTOK];
__device__ __half g_ctx[MTOT * CDIM];
__device__ __half g_Qh[NWIN * HEADS * LTOK * HD];
__device__ __half g_Kh[NWIN * HEADS * LTOK * HD];
__device__ __half g_Vh[NWIN * HEADS * LTOK * HD];
__device__ __half g_W1h[576 * 192];
__device__ __half g_W2h[192 * 192];

// ------------------------------ helpers ------------------------------------
__device__ __forceinline__ uint32_t smem_u32(const void* p) {
    uint32_t a;
    asm("{ .reg .u64 t; cvta.to.shared.u64 t, %1; cvt.u32.u64 %0, t; }"
        : "=r"(a) : "l"(p));
    return a;
}
__device__ __forceinline__ uint32_t pack_h2(float a, float b) {
    __half2 t = __floats2half2_rn(a, b);
    return *reinterpret_cast<uint32_t*>(&t);
}
// exp(x) on the FMA pipe
__device__ __forceinline__ float fexp(float x) {
    float y = fmaxf(x * 1.4426950408889634f, -126.0f);
    float n = rintf(y);
    float f = y - n;
    float p = 0.0013333558f;
    p = fmaf(p, f, 0.009618129f);
    p = fmaf(p, f, 0.055504109f);
    p = fmaf(p, f, 0.24022651f);
    p = fmaf(p, f, 0.69314718f);
    p = fmaf(p, f, 1.0f);
    return __int_as_float(((int)n + 127) << 23) * p;
}

#define LDSM_X4(r0, r1, r2, r3, addr)                                          \
    asm volatile("ldmatrix.sync.aligned.m8n8.x4.shared.b16 {%0,%1,%2,%3}, [%4];" \
                 : "=r"(r0), "=r"(r1), "=r"(r2), "=r"(r3) : "r"(addr))

#define MMA_F16(d, a, b)                                                       \
    asm volatile("mma.sync.aligned.m16n8k16.row.col.f32.f16.f16.f32 "          \
                 "{%0,%1,%2,%3}, {%4,%5,%6,%7}, {%8,%9}, {%0,%1,%2,%3};"       \
                 : "+f"((d)[0]), "+f"((d)[1]), "+f"((d)[2]), "+f"((d)[3])      \
                 : "r"((a)[0]), "r"((a)[1]), "r"((a)[2]), "r"((a)[3]),         \
                   "r"((b)[0]), "r"((b)[1]))

#define CP_ASYNC16(sm, gm)                                                     \
    asm volatile("cp.async.cg.shared.global [%0], [%1], 16;"                   \
                 :: "r"(sm), "l"(gm) : "memory")
#define CP_COMMIT() asm volatile("cp.async.commit_group;" ::: "memory")
#define CP_WAIT0()  asm volatile("cp.async.wait_group 0;" ::: "memory")

// ---------------------------------------------------------------------------
// Prep: W [192][N] fp32 -> [N][192] fp16 hi
// ---------------------------------------------------------------------------
__global__ void splitW_kernel(const float* __restrict__ W,
                              __half* __restrict__ h, int N) {
    int idx = blockIdx.x * blockDim.x + threadIdx.x;
    if (idx >= N * 192) return;
    int n = idx / 192, k = idx - n * 192;
    h[idx] = __float2half_rn(W[(size_t)k * N + n]);
}

// ---------------------------------------------------------------------------
// K0: bias gather — one element per thread (max TLP on the 2-deep chain)
//   grid = NW * 81, block = 256 (81*256 = 20736 = LTOK*LTOK)
// ---------------------------------------------------------------------------
__global__ void bias_gather_kernel(const float* __restrict__ table,
                                   const int* __restrict__ pidx) {
    const int nw = blockIdx.x / 81;
    const int i  = (blockIdx.x % 81) * 256 + threadIdx.x;
    const int pi = pidx[i];
    const float2* src = reinterpret_cast<const float2*>(
        table + (size_t)pi * (NW * HEADS) + nw * HEADS);
    float2 a = src[0], b = src[1], c = src[2];
    const size_t dbase = (size_t)nw * HEADS * (LTOK * LTOK);
    g_bias[dbase + 0 * (LTOK * LTOK) + i] = __float2half_rn(a.x);
    g_bias[dbase + 1 * (LTOK * LTOK) + i] = __float2half_rn(a.y);
    g_bias[dbase + 2 * (LTOK * LTOK) + i] = __float2half_rn(b.x);
    g_bias[dbase + 3 * (LTOK * LTOK) + i] = __float2half_rn(b.y);
    g_bias[dbase + 4 * (LTOK * LTOK) + i] = __float2half_rn(c.x);
    g_bias[dbase + 5 * (LTOK * LTOK) + i] = __float2half_rn(c.y);
}

// ---------------------------------------------------------------------------
// fp16 1-pass GEMM, cp.async pipelined.
// mode 0: A fp32 -> scatter Qh(scaled)/Kh/Vh head-major; mode 1: A fp16 -> out.
// ---------------------------------------------------------------------------
#define ASTR 200
#define GEMM_SMEM ((128 * ASTR + 64 * ASTR) * 2)  // 76800 B

__global__ __launch_bounds__(256, 2) void mma_gemm_kernel(
    const void* __restrict__ Ain, const __half* __restrict__ Bh,
    const float* __restrict__ bias, int ntiles, int mode,
    float* __restrict__ out) {
    extern __shared__ __align__(16) __half sb[];
    __half* sA  = sb;                      // [128][ASTR]
    __half* sBh = sb + 128 * ASTR;         // [64][ASTR]

    const int tid = threadIdx.x;
    const int warp = tid >> 5, lane = tid & 31;
    const int warpm = warp >> 1, warpn = warp & 1;
    const int m_blk = blockIdx.x * 128;

    // ---- issue B tile 0 loads (async) ----
    {
#pragma unroll
        for (int it = 0; it < 6; it++) {
            int i = tid + it * 256;
            int r = i / 24, c = (i % 24) * 8;
            CP_ASYNC16(smem_u32(&sBh[r * ASTR + c]),
                       (const void*)&Bh[(size_t)r * 192 + c]);
        }
        CP_COMMIT();
    }

    // ---- stage A ----
    if (mode == 1) {
        const __half* A = (const __half*)Ain;
        for (int i = tid; i < 128 * 24; i += 256) {
            int r = i / 24, c = (i % 24) * 8;
            *reinterpret_cast<uint4*>(&sA[r * ASTR + c]) =
                *reinterpret_cast<const uint4*>(&A[(size_t)(m_blk + r) * 192 + c]);
        }
    } else {
        const float* A = (const float*)Ain;
        for (int i = tid; i < 128 * 48; i += 256) {
            int r = i / 48, c4 = (i % 48) * 4;
            float4 v = *reinterpret_cast<const float4*>(&A[(size_t)(m_blk + r) * 192 + c4]);
            *reinterpret_cast<__half2*>(&sA[r * ASTR + c4]) = __floats2half2_rn(v.x, v.y);
            *reinterpret_cast<__half2*>(&sA[r * ASTR + c4 + 2]) = __floats2half2_rn(v.z, v.w);
        }
    }
    CP_WAIT0();
    __syncthreads();

    const int lr = lane & 7, sel = lane >> 3;
    const int a_row_off = lr + (sel & 1) * 8;
    const int a_col_off = (sel >> 1) * 8;
    const int b_row_off = lr + (sel >> 1) * 8;
    const int b_col_off = (sel & 1) * 8;
    const int qrow = lane >> 2;
    const int qcol = (lane & 3) * 2;

    int rbi[4], rli[4];
#pragma unroll
    for (int i = 0; i < 4; i++) {
        int r = m_blk + warpm * 32 + (i >> 1) * 16 + (i & 1) * 8 + qrow;
        rbi[i] = r / LTOK;
        rli[i] = r - rbi[i] * LTOK;
    }

    for (int nt = 0; nt < ntiles; nt++) {
        float acc[2][4][4];
#pragma unroll
        for (int mt = 0; mt < 2; mt++)
#pragma unroll
            for (int t4 = 0; t4 < 4; t4++)
#pragma unroll
                for (int j = 0; j < 4; j++) acc[mt][t4][j] = 0.f;

#pragma unroll 4
        for (int ks = 0; ks < 12; ks++) {
            const int k0 = ks * 16;
            uint32_t a[2][4], bh[4][2];
#pragma unroll
            for (int mt = 0; mt < 2; mt++) {
                int row = warpm * 32 + mt * 16 + a_row_off;
                LDSM_X4(a[mt][0], a[mt][1], a[mt][2], a[mt][3],
                        smem_u32(&sA[row * ASTR + k0 + a_col_off]));
            }
#pragma unroll
            for (int pr = 0; pr < 2; pr++) {
                int row = warpn * 32 + pr * 16 + b_row_off;
                LDSM_X4(bh[2 * pr][0], bh[2 * pr][1], bh[2 * pr + 1][0],
                        bh[2 * pr + 1][1],
                        smem_u32(&sBh[row * ASTR + k0 + b_col_off]));
            }
#pragma unroll
            for (int mt = 0; mt < 2; mt++)
#pragma unroll
                for (int t4 = 0; t4 < 4; t4++)
                    MMA_F16(acc[mt][t4], a[mt], bh[t4]);
        }
        __syncthreads();  // all warps done reading sB

        // ---- issue next B tile loads (hidden under epilogue) ----
        if (nt + 1 < ntiles) {
            const size_t nb = (size_t)(nt + 1) * 64;
#pragma unroll
            for (int it = 0; it < 6; it++) {
                int i = tid + it * 256;
                int r = i / 24, c = (i % 24) * 8;
                CP_ASYNC16(smem_u32(&sBh[r * ASTR + c]),
                           (const void*)&Bh[(nb + r) * 192 + c]);
            }
            CP_COMMIT();
        }

        // ---- epilogue(nt) ----
        if (mode == 1) {
#pragma unroll
            for (int t4 = 0; t4 < 4; t4++) {
                const int col = nt * 64 + warpn * 32 + t4 * 8 + qcol;
                const float b0 = bias[col], b1 = bias[col + 1];
#pragma unroll
                for (int mt = 0; mt < 2; mt++) {
                    const int r0 = m_blk + warpm * 32 + mt * 16 + qrow;
                    *reinterpret_cast<float2*>(&out[(size_t)r0 * CDIM + col]) =
                        make_float2(acc[mt][t4][0] + b0, acc[mt][t4][1] + b1);
                    *reinterpret_cast<float2*>(&out[(size_t)(r0 + 8) * CDIM + col]) =
                        make_float2(acc[mt][t4][2] + b0, acc[mt][t4][3] + b1);
                }
            }
        } else {
#pragma unroll
            for (int t4 = 0; t4 < 4; t4++) {
                const int col = nt * 64 + warpn * 32 + t4 * 8 + qcol;
                const int t = (col >= 2 * CDIM) ? 2 : ((col >= CDIM) ? 1 : 0);
                const int rem = col - t * CDIM;
                const int hh = rem >> 5, dd = rem & 31;
                const float b0 = bias[col], b1 = bias[col + 1];
                __half* dst = (t == 0) ? g_Qh : ((t == 1) ? g_Kh : g_Vh);
                const float sc = (t == 0) ? QK_SCALE : 1.0f;
#pragma unroll
                for (int mt = 0; mt < 2; mt++) {
                    const int i0 = mt * 2, i1 = mt * 2 + 1;
                    const size_t o0 =
                        ((size_t)(rbi[i0] * HEADS + hh) * LTOK + rli[i0]) * HD + dd;
                    const size_t o1 =
                        ((size_t)(rbi[i1] * HEADS + hh) * LTOK + rli[i1]) * HD + dd;
                    *reinterpret_cast<__half2*>(dst + o0) = __floats2half2_rn(
                        (acc[mt][t4][0] + b0) * sc, (acc[mt][t4][1] + b1) * sc);
                    *reinterpret_cast<__half2*>(dst + o1) = __floats2half2_rn(
                        (acc[mt][t4][2] + b0) * sc, (acc[mt][t4][3] + b1) * sc);
                }
            }
        }
        if (nt + 1 < ntiles) CP_WAIT0();
        __syncthreads();
    }
}

// ---------------------------------------------------------------------------
// K2: online-softmax mma attention. S = Qh@Kh, PV = P@Vh (both 1-pass).
// 288 thr, 2 CTA/SM, 32.8 KB SMEM.
// ---------------------------------------------------------------------------
#define QSTR 40
#define VTSTR 152
#define ATTN_SMEM (2 * 144 * QSTR * 2 + 32 * VTSTR * 2)   // 32768 B

__global__ __launch_bounds__(288, 2) void attn_mma_kernel(const float* __restrict__ mask) {
    extern __shared__ __align__(16) char sraw[];
    __half* sQh = reinterpret_cast<__half*>(sraw);
    __half* sKh = sQh + 144 * QSTR;
    __half* sVh = sKh + 144 * QSTR;          // [32][VTSTR] transposed

    const int bh = blockIdx.x;
    const int b = bh / HEADS, h = bh % HEADS;
    const int nw = b / WWINS;
    const int tid = threadIdx.x;
    const int warp = tid >> 5, lane = tid & 31;
    const size_t base = (size_t)bh * (LTOK * HD);

    for (int c = tid; c < 576; c += 288) {
        int l = c >> 2, dp = (c & 3) * 8;
        *reinterpret_cast<uint4*>(&sQh[l * QSTR + dp]) =
            *reinterpret_cast<const uint4*>(&g_Qh[base + l * 32 + dp]);
        *reinterpret_cast<uint4*>(&sKh[l * QSTR + dp]) =
            *reinterpret_cast<const uint4*>(&g_Kh[base + l * 32 + dp]);
    }
    for (int i = tid; i < 2304; i += 288) {
        int l = i >> 4, d2 = (i & 15) * 2;
        __half2 vh = *reinterpret_cast<const __half2*>(&g_Vh[base + l * 32 + d2]);
        sVh[d2 * VTSTR + l] = __low2half(vh);
        sVh[(d2 + 1) * VTSTR + l] = __high2half(vh);
    }
    __syncthreads();

    const int lr = lane & 7, sel = lane >> 3;
    const int arow = lr + (sel & 1) * 8, acol = (sel >> 1) * 8;
    const int brow = lr + (sel >> 1) * 8, bcol = (sel & 1) * 8;
    const int g = lane >> 2, tg = lane & 3;

    uint32_t qh[2][4];
#pragma unroll
    for (int ks = 0; ks < 2; ks++) {
        LDSM_X4(qh[ks][0], qh[ks][1], qh[ks][2], qh[ks][3],
                smem_u32(&sQh[(warp * 16 + arow) * QSTR + ks * 16 + acol]));
    }

    const __half* biasrow = g_bias + (size_t)(nw * HEADS + h) * (LTOK * LTOK);
    const float* maskrow = mask + (size_t)b * (LTOK * LTOK);
    const int r0 = warp * 16 + g;
    const int r1 = r0 + 8;

    float m0 = -1e30f, m1 = -1e30f, s0 = 0.f, s1 = 0.f;
    float o[4][4];
#pragma unroll
    for (int nb = 0; nb < 4; nb++)
#pragma unroll
        for (int j = 0; j < 4; j++) o[nb][j] = 0.f;

#pragma unroll 1
    for (int ch = 0; ch < 3; ch++) {
        float acc[6][4];
#pragma unroll
        for (int nb = 0; nb < 6; nb++)
#pragma unroll
            for (int j = 0; j < 4; j++) acc[nb][j] = 0.f;

#pragma unroll
        for (int j = 0; j < 3; j++) {
            const int nt = 3 * ch + j;
#pragma unroll
            for (int ks = 0; ks < 2; ks++) {
                uint32_t kh[4];
                LDSM_X4(kh[0], kh[1], kh[2], kh[3],
                        smem_u32(&sKh[(nt * 16 + brow) * QSTR + ks * 16 + bcol]));
                MMA_F16(acc[2 * j],     qh[ks], kh + 0);
                MMA_F16(acc[2 * j + 1], qh[ks], kh + 2);
            }
        }

#pragma unroll
        for (int nb = 0; nb < 6; nb++) {
            const int cc = 48 * ch + nb * 8 + tg * 2;
            float2 b0 = __half22float2(
                *reinterpret_cast<const __half2*>(&biasrow[r0 * LTOK + cc]));
            float2 m0v = *reinterpret_cast<const float2*>(&maskrow[r0 * LTOK + cc]);
            float2 b1 = __half22float2(
                *reinterpret_cast<const __half2*>(&biasrow[r1 * LTOK + cc]));
            float2 m1v = *reinterpret_cast<const float2*>(&maskrow[r1 * LTOK + cc]);
            acc[nb][0] += b0.x + m0v.x;
            acc[nb][1] += b0.y + m0v.y;
            acc[nb][2] += b1.x + m1v.x;
            acc[nb][3] += b1.y + m1v.y;
        }

        float cm0 = -1e30f, cm1 = -1e30f;
#pragma unroll
        for (int nb = 0; nb < 6; nb++) {
            cm0 = fmaxf(cm0, fmaxf(acc[nb][0], acc[nb][1]));
            cm1 = fmaxf(cm1, fmaxf(acc[nb][2], acc[nb][3]));
        }
        cm0 = fmaxf(cm0, __shfl_xor_sync(0xffffffffu, cm0, 1));
        cm0 = fmaxf(cm0, __shfl_xor_sync(0xffffffffu, cm0, 2));
        cm1 = fmaxf(cm1, __shfl_xor_sync(0xffffffffu, cm1, 1));
        cm1 = fmaxf(cm1, __shfl_xor_sync(0xffffffffu, cm1, 2));
        const float nm0 = fmaxf(m0, cm0);
        const float nm1 = fmaxf(m1, cm1);
        const float sc0 = fexp(m0 - nm0);
        const float sc1 = fexp(m1 - nm1);
        m0 = nm0; m1 = nm1;
        s0 *= sc0; s1 *= sc1;
#pragma unroll
        for (int nb = 0; nb < 4; nb++) {
            o[nb][0] *= sc0; o[nb][1] *= sc0;
            o[nb][2] *= sc1; o[nb][3] *= sc1;
        }

#pragma unroll
        for (int nb = 0; nb < 6; nb++) {
            acc[nb][0] = fexp(acc[nb][0] - nm0);
            acc[nb][1] = fexp(acc[nb][1] - nm0);
            acc[nb][2] = fexp(acc[nb][2] - nm1);
            acc[nb][3] = fexp(acc[nb][3] - nm1);
            s0 += acc[nb][0] + acc[nb][1];
            s1 += acc[nb][2] + acc[nb][3];
        }

#pragma unroll
        for (int k = 0; k < 3; k++) {
            const int ksg = 3 * ch + k;
            uint32_t a[4];
            a[0] = pack_h2(acc[2 * k][0], acc[2 * k][1]);
            a[1] = pack_h2(acc[2 * k][2], acc[2 * k][3]);
            a[2] = pack_h2(acc[2 * k + 1][0], acc[2 * k + 1][1]);
            a[3] = pack_h2(acc[2 * k + 1][2], acc[2 * k + 1][3]);
#pragma unroll
            for (int ntv = 0; ntv < 2; ntv++) {
                uint32_t vh[4];
                LDSM_X4(vh[0], vh[1], vh[2], vh[3],
                        smem_u32(&sVh[(ntv * 16 + brow) * VTSTR + ksg * 16 + bcol]));
                MMA_F16(o[2 * ntv],     a, vh + 0);
                MMA_F16(o[2 * ntv + 1], a, vh + 2);
            }
        }
    }

    s0 += __shfl_xor_sync(0xffffffffu, s0, 1);
    s0 += __shfl_xor_sync(0xffffffffu, s0, 2);
    s1 += __shfl_xor_sync(0xffffffffu, s1, 1);
    s1 += __shfl_xor_sync(0xffffffffu, s1, 2);
    const float inv0 = 1.f / s0, inv1 = 1.f / s1;

#pragma unroll
    for (int nb = 0; nb < 4; nb++) {
        const int d0 = nb * 8 + tg * 2;
        const size_t off0 = ((size_t)b * LTOK + r0) * CDIM + h * HD + d0;
        const size_t off1 = ((size_t)b * LTOK + r1) * CDIM + h * HD + d0;
        *reinterpret_cast<__half2*>(&g_ctx[off0]) =
            __floats2half2_rn(o[nb][0] * inv0, o[nb][1] * inv0);
        *reinterpret_cast<__half2*>(&g_ctx[off1]) =
            __floats2half2_rn(o[nb][2] * inv1, o[nb][3] * inv1);
    }
}

// ---------------------------------------------------------------------------
extern "C" void kernel_launch(void* const* d_in, const int* in_sizes, int n_in,
                              void* d_out, int out_size) {
    const float* x    = (const float*)d_in[0];
    const float* mask = (const float*)d_in[1];
    const float* W1   = (const float*)d_in[2];
    const float* b1   = (const float*)d_in[3];
    const float* W2   = (const float*)d_in[4];
    const float* b2   = (const float*)d_in[5];
    const float* btab = (const float*)d_in[6];
    const int*   pidx = (const int*)d_in[7];
    float* out = (float*)d_out;
    (void)in_sizes; (void)n_in; (void)out_size;

    cudaFuncSetAttribute(mma_gemm_kernel,
                         cudaFuncAttributeMaxDynamicSharedMemorySize, GEMM_SMEM);
    cudaFuncSetAttribute(attn_mma_kernel,
                         cudaFuncAttributeMaxDynamicSharedMemorySize, ATTN_SMEM);

    __half *w1h, *w2h, *ctx;
    cudaGetSymbolAddress((void**)&w1h, g_W1h);
    cudaGetSymbolAddress((void**)&w2h, g_W2h);
    cudaGetSymbolAddress((void**)&ctx, g_ctx);

    splitW_kernel<<<(576 * 192 + 255) / 256, 256>>>(W1, w1h, 576);
    splitW_kernel<<<(192 * 192 + 255) / 256, 256>>>(W2, w2h, 192);
    bias_gather_kernel<<<NW * 81, 256>>>(btab, pidx);

    mma_gemm_kernel<<<MTOT / 128, 256, GEMM_SMEM>>>(x, w1h, b1, 9, 0, nullptr);
    attn_mma_kernel<<<NWIN * HEADS, 288, ATTN_SMEM>>>(mask);
    mma_gemm_kernel<<<MTOT / 128, 256, GEMM_SMEM>>>(ctx, w2h, b2, 3, 1, out);
}